// round 1
// baseline (speedup 1.0000x reference)
#include <cuda_runtime.h>
#include <math.h>

#define BZ 32
#define HH 56
#define WW 56
#define DIM 256
#define HEADS 8
#define WS 7
#define SHIFT 3
#define NTOK 49
#define NWIN 64            // windows per image
#define HEAD_DIM 32
#define HIDDEN 1024
#define MTOT (BZ*HH*WW)    // 100352 rows

// ---------------- scratch (static device globals; no allocation) -------------
__device__ float g_hwin[(size_t)MTOT * DIM];      // LN1(+shift+partition) out, reused for LN2 out
__device__ float g_qkv [(size_t)MTOT * 3 * DIM];  // qkv
__device__ float g_attn[(size_t)MTOT * DIM];      // attention output (window layout)
__device__ float g_x1  [(size_t)MTOT * DIM];      // x + proj (spatial layout)
__device__ float g_h2  [(size_t)MTOT * HIDDEN];   // gelu(fc1) output

// row m in window layout -> row in spatial layout (applies window-reverse + unshift)
__device__ __forceinline__ int remap_row(int m) {
    int b    = m / (NWIN * NTOK);
    int rem  = m - b * (NWIN * NTOK);
    int wimg = rem / NTOK;
    int n    = rem - wimg * NTOK;
    int hh = (wimg >> 3) * WS + n / WS + SHIFT; if (hh >= HH) hh -= HH;
    int ww = (wimg & 7) * WS + n % WS + SHIFT;  if (ww >= WW) ww -= WW;
    return b * (HH * WW) + hh * WW + ww;
}

// ---------------- LayerNorm (one warp per 256-wide row) ----------------------
// SHIFTMAP=true: gather rows through the shift+window-partition mapping.
template<bool SHIFTMAP>
__global__ void __launch_bounds__(256) ln_kernel(const float* __restrict__ x,
                                                 const float* __restrict__ gw,
                                                 const float* __restrict__ gb,
                                                 float* __restrict__ out) {
    int warp = threadIdx.x >> 5, lane = threadIdx.x & 31;
    int m = blockIdx.x * 8 + warp;
    const float* xr;
    if (SHIFTMAP) {
        int r = remap_row(m);     // same formula maps window-token -> spatial source
        xr = x + (size_t)r * DIM;
    } else {
        xr = x + (size_t)m * DIM;
    }
    float4 v0 = *(const float4*)(xr + lane * 4);
    float4 v1 = *(const float4*)(xr + 128 + lane * 4);
    float s  = v0.x + v0.y + v0.z + v0.w + v1.x + v1.y + v1.z + v1.w;
    float sq = v0.x*v0.x + v0.y*v0.y + v0.z*v0.z + v0.w*v0.w
             + v1.x*v1.x + v1.y*v1.y + v1.z*v1.z + v1.w*v1.w;
    #pragma unroll
    for (int o = 16; o; o >>= 1) {
        s  += __shfl_xor_sync(0xffffffffu, s,  o);
        sq += __shfl_xor_sync(0xffffffffu, sq, o);
    }
    float mu  = s * (1.0f / DIM);
    float var = sq * (1.0f / DIM) - mu * mu;
    float rs  = rsqrtf(var + 1e-5f);
    float4 w0 = *(const float4*)(gw + lane * 4);
    float4 w1 = *(const float4*)(gw + 128 + lane * 4);
    float4 b0 = *(const float4*)(gb + lane * 4);
    float4 b1 = *(const float4*)(gb + 128 + lane * 4);
    float4 o0, o1;
    o0.x = (v0.x - mu) * rs * w0.x + b0.x;  o0.y = (v0.y - mu) * rs * w0.y + b0.y;
    o0.z = (v0.z - mu) * rs * w0.z + b0.z;  o0.w = (v0.w - mu) * rs * w0.w + b0.w;
    o1.x = (v1.x - mu) * rs * w1.x + b1.x;  o1.y = (v1.y - mu) * rs * w1.y + b1.y;
    o1.z = (v1.z - mu) * rs * w1.z + b1.z;  o1.w = (v1.w - mu) * rs * w1.w + b1.w;
    float* orow = out + (size_t)m * DIM;
    *(float4*)(orow + lane * 4)       = o0;
    *(float4*)(orow + 128 + lane * 4) = o1;
}

// ---------------- SGEMM (NT: A[M,K] row-major, B[N,K] row-major) -------------
// 128x128 tile, BK=16, 256 threads, 8x8 per thread.
// EPI: 0 = +bias (qkv)
//      1 = +bias, exact GELU (fc1)
//      2 = +bias, scatter row via remap_row, add res (proj -> x1)
//      3 = +bias, add res at same row (fc2 -> d_out)
template<int EPI>
__global__ void __launch_bounds__(256) sgemm_nt(const float* __restrict__ A,
                                               const float* __restrict__ Bm,
                                               const float* __restrict__ bias,
                                               float* __restrict__ C,
                                               int M, int N, int K,
                                               const float* __restrict__ res) {
    __shared__ float As[16][132];
    __shared__ float Bs[16][132];
    int tid = threadIdx.x;
    int bn = blockIdx.x, bm = blockIdx.y;

    int lrow = tid >> 2;              // 0..63
    int lk4  = (tid & 3) * 4;         // 0,4,8,12
    const float* Ag = A  + (size_t)(bm * 128 + lrow) * K + lk4;
    const float* Bg = Bm + (size_t)(bn * 128 + lrow) * K + lk4;

    int warp = tid >> 5, lane = tid & 31;
    int wr = warp & 3, wc = warp >> 2;            // 4x2 warp grid
    int row0 = wr * 32 + (lane >> 3) * 8;         // thread 8 rows
    int col0 = wc * 64 + (lane & 7) * 8;          // thread 8 cols

    float acc[8][8];
    #pragma unroll
    for (int i = 0; i < 8; i++)
        #pragma unroll
        for (int j = 0; j < 8; j++) acc[i][j] = 0.0f;

    for (int k0 = 0; k0 < K; k0 += 16) {
        float4 a0 = *(const float4*)(Ag);
        float4 a1 = *(const float4*)(Ag + (size_t)64 * K);
        float4 b0 = *(const float4*)(Bg);
        float4 b1 = *(const float4*)(Bg + (size_t)64 * K);
        Ag += 16; Bg += 16;
        __syncthreads();
        As[lk4 + 0][lrow] = a0.x; As[lk4 + 1][lrow] = a0.y;
        As[lk4 + 2][lrow] = a0.z; As[lk4 + 3][lrow] = a0.w;
        As[lk4 + 0][lrow + 64] = a1.x; As[lk4 + 1][lrow + 64] = a1.y;
        As[lk4 + 2][lrow + 64] = a1.z; As[lk4 + 3][lrow + 64] = a1.w;
        Bs[lk4 + 0][lrow] = b0.x; Bs[lk4 + 1][lrow] = b0.y;
        Bs[lk4 + 2][lrow] = b0.z; Bs[lk4 + 3][lrow] = b0.w;
        Bs[lk4 + 0][lrow + 64] = b1.x; Bs[lk4 + 1][lrow + 64] = b1.y;
        Bs[lk4 + 2][lrow + 64] = b1.z; Bs[lk4 + 3][lrow + 64] = b1.w;
        __syncthreads();
        #pragma unroll
        for (int k = 0; k < 16; k++) {
            float4 ra0 = *(const float4*)&As[k][row0];
            float4 ra1 = *(const float4*)&As[k][row0 + 4];
            float4 rb0 = *(const float4*)&Bs[k][col0];
            float4 rb1 = *(const float4*)&Bs[k][col0 + 4];
            float ar[8] = {ra0.x, ra0.y, ra0.z, ra0.w, ra1.x, ra1.y, ra1.z, ra1.w};
            float br[8] = {rb0.x, rb0.y, rb0.z, rb0.w, rb1.x, rb1.y, rb1.z, rb1.w};
            #pragma unroll
            for (int i = 0; i < 8; i++)
                #pragma unroll
                for (int j = 0; j < 8; j++)
                    acc[i][j] += ar[i] * br[j];
        }
    }

    float bcol[8];
    #pragma unroll
    for (int j = 0; j < 8; j++) bcol[j] = bias[bn * 128 + col0 + j];

    #pragma unroll
    for (int i = 0; i < 8; i++) {
        int gm = bm * 128 + row0 + i;
        int gc = bn * 128 + col0;
        float v[8];
        #pragma unroll
        for (int j = 0; j < 8; j++) v[j] = acc[i][j] + bcol[j];
        if (EPI == 1) {
            #pragma unroll
            for (int j = 0; j < 8; j++)
                v[j] = 0.5f * v[j] * (1.0f + erff(v[j] * 0.70710678118654752f));
        }
        int orow = gm;
        if (EPI == 2) orow = remap_row(gm);
        if (EPI == 2 || EPI == 3) {
            const float* rr = res + (size_t)orow * N + gc;
            #pragma unroll
            for (int j = 0; j < 8; j++) v[j] += rr[j];
        }
        float* cp = C + (size_t)orow * N + gc;
        float4 s0 = make_float4(v[0], v[1], v[2], v[3]);
        float4 s1 = make_float4(v[4], v[5], v[6], v[7]);
        *(float4*)(cp)     = s0;
        *(float4*)(cp + 4) = s1;
    }
}

// ---------------- windowed attention: one block per (window, head) -----------
__global__ void __launch_bounds__(256) attn_kernel(const float* __restrict__ qkv,
                                                   const float* __restrict__ rpb,
                                                   const int* __restrict__ rel_idx,
                                                   const float* __restrict__ mask,
                                                   float* __restrict__ out) {
    int wwin = blockIdx.x;                   // 0..2047
    int head = blockIdx.y;                   // 0..7
    __shared__ float qs[NTOK * 33];
    __shared__ float ks[NTOK * 33];
    __shared__ float vs[NTOK * 33];
    __shared__ float bm[NTOK * 50];
    __shared__ float pr[8][64];

    int tid = threadIdx.x;
    const float* base = qkv + (size_t)wwin * NTOK * (3 * DIM) + head * HEAD_DIM;
    for (int idx = tid; idx < NTOK * 32; idx += 256) {
        int n = idx >> 5, d = idx & 31;
        const float* rowp = base + (size_t)n * (3 * DIM);
        qs[n * 33 + d] = rowp[d];
        ks[n * 33 + d] = rowp[DIM + d];
        vs[n * 33 + d] = rowp[2 * DIM + d];
    }
    const float* mk = mask + (size_t)(wwin & 63) * (NTOK * NTOK);
    for (int idx = tid; idx < NTOK * NTOK; idx += 256) {
        int n = idx / NTOK, mcol = idx - n * NTOK;
        bm[n * 50 + mcol] = rpb[rel_idx[idx] * HEADS + head] + mk[idx];
    }
    __syncthreads();

    int warp = tid >> 5, lane = tid & 31;
    const float scale = 0.17677669529663687f;   // 1/sqrt(32)

    for (int n = warp; n < NTOK; n += 8) {
        int m0 = lane, m1 = lane + 32;
        int m1c = (m1 < NTOK) ? m1 : (NTOK - 1);
        float a0 = 0.0f, a1 = 0.0f;
        #pragma unroll
        for (int d = 0; d < 32; d++) {
            float qd = qs[n * 33 + d];
            a0 += qd * ks[m0 * 33 + d];
            a1 += qd * ks[m1c * 33 + d];
        }
        float s0 = a0 * scale + bm[n * 50 + m0];
        float s1 = (m1 < NTOK) ? (a1 * scale + bm[n * 50 + m1]) : -1e30f;
        float mx = fmaxf(s0, s1);
        #pragma unroll
        for (int o = 16; o; o >>= 1) mx = fmaxf(mx, __shfl_xor_sync(0xffffffffu, mx, o));
        float e0 = expf(s0 - mx);
        float e1 = (m1 < NTOK) ? expf(s1 - mx) : 0.0f;
        float sm = e0 + e1;
        #pragma unroll
        for (int o = 16; o; o >>= 1) sm += __shfl_xor_sync(0xffffffffu, sm, o);
        float inv = 1.0f / sm;
        pr[warp][m0] = e0 * inv;
        if (m1 < NTOK) pr[warp][m1] = e1 * inv;
        __syncwarp();
        float acc = 0.0f;
        #pragma unroll
        for (int m = 0; m < NTOK; m++) acc += pr[warp][m] * vs[m * 33 + lane];
        out[((size_t)wwin * NTOK + n) * DIM + head * HEAD_DIM + lane] = acc;
        __syncwarp();
    }
}

// ---------------- launcher ---------------------------------------------------
extern "C" void kernel_launch(void* const* d_in, const int* in_sizes, int n_in,
                              void* d_out, int out_size) {
    const float* x     = (const float*)d_in[0];
    const float* n1w   = (const float*)d_in[1];
    const float* n1b   = (const float*)d_in[2];
    const float* qkvw  = (const float*)d_in[3];
    const float* qkvb  = (const float*)d_in[4];
    const float* rpb   = (const float*)d_in[5];
    const float* projw = (const float*)d_in[6];
    const float* projb = (const float*)d_in[7];
    const float* n2w   = (const float*)d_in[8];
    const float* n2b   = (const float*)d_in[9];
    const float* fc1w  = (const float*)d_in[10];
    const float* fc1b  = (const float*)d_in[11];
    const float* fc2w  = (const float*)d_in[12];
    const float* fc2b  = (const float*)d_in[13];
    const int*   relix = (const int*)d_in[14];
    const float* amask = (const float*)d_in[15];
    float* out = (float*)d_out;

    float *hwin, *qkv, *attn, *x1, *h2;
    cudaGetSymbolAddress((void**)&hwin, g_hwin);
    cudaGetSymbolAddress((void**)&qkv,  g_qkv);
    cudaGetSymbolAddress((void**)&attn, g_attn);
    cudaGetSymbolAddress((void**)&x1,   g_x1);
    cudaGetSymbolAddress((void**)&h2,   g_h2);

    // 1. LN1 + shift + window-partition
    ln_kernel<true><<<MTOT / 8, 256>>>(x, n1w, n1b, hwin);
    // 2. QKV GEMM: [100352,256] x [768,256]^T
    sgemm_nt<0><<<dim3(3 * DIM / 128, MTOT / 128), 256>>>(hwin, qkvw, qkvb, qkv,
                                                          MTOT, 3 * DIM, DIM, nullptr);
    // 3. windowed attention
    attn_kernel<<<dim3(BZ * NWIN, HEADS), 256>>>(qkv, rpb, relix, amask, attn);
    // 4. proj GEMM + window-reverse scatter + residual -> x1
    sgemm_nt<2><<<dim3(DIM / 128, MTOT / 128), 256>>>(attn, projw, projb, x1,
                                                      MTOT, DIM, DIM, x);
    // 5. LN2
    ln_kernel<false><<<MTOT / 8, 256>>>(x1, n2w, n2b, hwin);
    // 6. FC1 + GELU
    sgemm_nt<1><<<dim3(HIDDEN / 128, MTOT / 128), 256>>>(hwin, fc1w, fc1b, h2,
                                                         MTOT, HIDDEN, DIM, nullptr);
    // 7. FC2 + residual -> out
    sgemm_nt<3><<<dim3(DIM / 128, MTOT / 128), 256>>>(h2, fc2w, fc2b, out,
                                                      MTOT, DIM, HIDDEN, x1);
}

// round 2
// speedup vs baseline: 1.3758x; 1.3758x over previous
#include <cuda_runtime.h>
#include <math.h>
#include <stdint.h>

#define BZ 32
#define HH 56
#define WW 56
#define DIM 256
#define HEADS 8
#define WS 7
#define SHIFT 3
#define NTOK 49
#define NWIN 64
#define HEAD_DIM 32
#define HIDDEN 1024
#define MTOT (BZ*HH*WW)    // 100352 rows

// ---------------- scratch ----------------------------------------------------
__device__ float g_hwin[(size_t)MTOT * DIM];
__device__ float g_qkv [(size_t)MTOT * 3 * DIM];
__device__ float g_attn[(size_t)MTOT * DIM];
__device__ float g_x1  [(size_t)MTOT * DIM];
__device__ float g_h2  [(size_t)MTOT * HIDDEN];

__device__ __forceinline__ int remap_row(int m) {
    int b    = m / (NWIN * NTOK);
    int rem  = m - b * (NWIN * NTOK);
    int wimg = rem / NTOK;
    int n    = rem - wimg * NTOK;
    int hh = (wimg >> 3) * WS + n / WS + SHIFT; if (hh >= HH) hh -= HH;
    int ww = (wimg & 7) * WS + n % WS + SHIFT;  if (ww >= WW) ww -= WW;
    return b * (HH * WW) + hh * WW + ww;
}

__device__ __forceinline__ uint32_t f2tf(float x) {
    uint32_t r;
    asm("cvt.rna.tf32.f32 %0, %1;" : "=r"(r) : "f"(x));
    return r;
}

__device__ __forceinline__ void mma_tf32(float* d, const uint32_t* a, const uint32_t* b) {
    asm volatile(
        "mma.sync.aligned.m16n8k8.row.col.f32.tf32.tf32.f32 "
        "{%0,%1,%2,%3}, {%4,%5,%6,%7}, {%8,%9}, {%0,%1,%2,%3};\n"
        : "+f"(d[0]), "+f"(d[1]), "+f"(d[2]), "+f"(d[3])
        : "r"(a[0]), "r"(a[1]), "r"(a[2]), "r"(a[3]), "r"(b[0]), "r"(b[1]));
}

// ---------------- LayerNorm --------------------------------------------------
template<bool SHIFTMAP>
__global__ void __launch_bounds__(256) ln_kernel(const float* __restrict__ x,
                                                 const float* __restrict__ gw,
                                                 const float* __restrict__ gb,
                                                 float* __restrict__ out) {
    int warp = threadIdx.x >> 5, lane = threadIdx.x & 31;
    int m = blockIdx.x * 8 + warp;
    const float* xr;
    if (SHIFTMAP) {
        int r = remap_row(m);
        xr = x + (size_t)r * DIM;
    } else {
        xr = x + (size_t)m * DIM;
    }
    float4 v0 = *(const float4*)(xr + lane * 4);
    float4 v1 = *(const float4*)(xr + 128 + lane * 4);
    float s  = v0.x + v0.y + v0.z + v0.w + v1.x + v1.y + v1.z + v1.w;
    float sq = v0.x*v0.x + v0.y*v0.y + v0.z*v0.z + v0.w*v0.w
             + v1.x*v1.x + v1.y*v1.y + v1.z*v1.z + v1.w*v1.w;
    #pragma unroll
    for (int o = 16; o; o >>= 1) {
        s  += __shfl_xor_sync(0xffffffffu, s,  o);
        sq += __shfl_xor_sync(0xffffffffu, sq, o);
    }
    float mu  = s * (1.0f / DIM);
    float var = sq * (1.0f / DIM) - mu * mu;
    float rs  = rsqrtf(var + 1e-5f);
    float4 w0 = *(const float4*)(gw + lane * 4);
    float4 w1 = *(const float4*)(gw + 128 + lane * 4);
    float4 b0 = *(const float4*)(gb + lane * 4);
    float4 b1 = *(const float4*)(gb + 128 + lane * 4);
    float4 o0, o1;
    o0.x = (v0.x - mu) * rs * w0.x + b0.x;  o0.y = (v0.y - mu) * rs * w0.y + b0.y;
    o0.z = (v0.z - mu) * rs * w0.z + b0.z;  o0.w = (v0.w - mu) * rs * w0.w + b0.w;
    o1.x = (v1.x - mu) * rs * w1.x + b1.x;  o1.y = (v1.y - mu) * rs * w1.y + b1.y;
    o1.z = (v1.z - mu) * rs * w1.z + b1.z;  o1.w = (v1.w - mu) * rs * w1.w + b1.w;
    float* orow = out + (size_t)m * DIM;
    *(float4*)(orow + lane * 4)       = o0;
    *(float4*)(orow + 128 + lane * 4) = o1;
}

// ---------------- tf32 tensor-core GEMM (NT) --------------------------------
// A[M,K] row-major, B[N,K] row-major. 128x128 tile, BK=16, 256 threads.
// Warp grid 2(m) x 4(n); warp tile 64x32 = 4x4 m16n8k8 fragments.
// EPI: 0=+bias  1=+bias,GELU  2=+bias,remap-scatter,+res  3=+bias,+res
template<int EPI>
__global__ void __launch_bounds__(256, 1) tgemm_nt(const float* __restrict__ A,
                                                  const float* __restrict__ Bm,
                                                  const float* __restrict__ bias,
                                                  float* __restrict__ C,
                                                  int M, int N, int K,
                                                  const float* __restrict__ res) {
    __shared__ uint32_t As[2][16][132];
    __shared__ uint32_t Bs[2][16][132];
    int tid = threadIdx.x;
    int bn = blockIdx.x, bm = blockIdx.y;

    int lrow = tid >> 2;              // 0..63
    int lk4  = (tid & 3) * 4;         // 0,4,8,12
    const float* Ag = A  + (size_t)(bm * 128 + lrow) * K + lk4;
    const float* Bg = Bm + (size_t)(bn * 128 + lrow) * K + lk4;

    int warp = tid >> 5, lane = tid & 31;
    int warpM = (warp & 1) * 64;
    int warpN = (warp >> 1) * 32;
    int r = lane >> 2, c = lane & 3;

    float acc[4][4][4];
    #pragma unroll
    for (int mi = 0; mi < 4; mi++)
        #pragma unroll
        for (int ni = 0; ni < 4; ni++)
            #pragma unroll
            for (int t = 0; t < 4; t++) acc[mi][ni][t] = 0.0f;

    // prologue: load tile k=0, store to buf 0
    float4 a0 = *(const float4*)(Ag);
    float4 a1 = *(const float4*)(Ag + (size_t)64 * K);
    float4 b0 = *(const float4*)(Bg);
    float4 b1 = *(const float4*)(Bg + (size_t)64 * K);
    Ag += 16; Bg += 16;
    {
        As[0][lk4+0][lrow] = f2tf(a0.x); As[0][lk4+1][lrow] = f2tf(a0.y);
        As[0][lk4+2][lrow] = f2tf(a0.z); As[0][lk4+3][lrow] = f2tf(a0.w);
        As[0][lk4+0][lrow+64] = f2tf(a1.x); As[0][lk4+1][lrow+64] = f2tf(a1.y);
        As[0][lk4+2][lrow+64] = f2tf(a1.z); As[0][lk4+3][lrow+64] = f2tf(a1.w);
        Bs[0][lk4+0][lrow] = f2tf(b0.x); Bs[0][lk4+1][lrow] = f2tf(b0.y);
        Bs[0][lk4+2][lrow] = f2tf(b0.z); Bs[0][lk4+3][lrow] = f2tf(b0.w);
        Bs[0][lk4+0][lrow+64] = f2tf(b1.x); Bs[0][lk4+1][lrow+64] = f2tf(b1.y);
        Bs[0][lk4+2][lrow+64] = f2tf(b1.z); Bs[0][lk4+3][lrow+64] = f2tf(b1.w);
    }
    __syncthreads();

    int buf = 0;
    for (int k0 = 16; ; k0 += 16) {
        bool more = (k0 < K);
        float4 na0, na1, nb0, nb1;
        if (more) {
            na0 = *(const float4*)(Ag);
            na1 = *(const float4*)(Ag + (size_t)64 * K);
            nb0 = *(const float4*)(Bg);
            nb1 = *(const float4*)(Bg + (size_t)64 * K);
            Ag += 16; Bg += 16;
        }
        // compute on current buffer
        #pragma unroll
        for (int kk = 0; kk < 16; kk += 8) {
            uint32_t af[4][4], bf[4][2];
            #pragma unroll
            for (int mi = 0; mi < 4; mi++) {
                int m0 = warpM + mi * 16 + r;
                af[mi][0] = As[buf][kk + c][m0];
                af[mi][1] = As[buf][kk + c][m0 + 8];
                af[mi][2] = As[buf][kk + c + 4][m0];
                af[mi][3] = As[buf][kk + c + 4][m0 + 8];
            }
            #pragma unroll
            for (int ni = 0; ni < 4; ni++) {
                int n0 = warpN + ni * 8 + r;
                bf[ni][0] = Bs[buf][kk + c][n0];
                bf[ni][1] = Bs[buf][kk + c + 4][n0];
            }
            #pragma unroll
            for (int mi = 0; mi < 4; mi++)
                #pragma unroll
                for (int ni = 0; ni < 4; ni++)
                    mma_tf32(acc[mi][ni], af[mi], bf[ni]);
        }
        if (!more) break;
        __syncthreads();
        int nb = buf ^ 1;
        As[nb][lk4+0][lrow] = f2tf(na0.x); As[nb][lk4+1][lrow] = f2tf(na0.y);
        As[nb][lk4+2][lrow] = f2tf(na0.z); As[nb][lk4+3][lrow] = f2tf(na0.w);
        As[nb][lk4+0][lrow+64] = f2tf(na1.x); As[nb][lk4+1][lrow+64] = f2tf(na1.y);
        As[nb][lk4+2][lrow+64] = f2tf(na1.z); As[nb][lk4+3][lrow+64] = f2tf(na1.w);
        Bs[nb][lk4+0][lrow] = f2tf(nb0.x); Bs[nb][lk4+1][lrow] = f2tf(nb0.y);
        Bs[nb][lk4+2][lrow] = f2tf(nb0.z); Bs[nb][lk4+3][lrow] = f2tf(nb0.w);
        Bs[nb][lk4+0][lrow+64] = f2tf(nb1.x); Bs[nb][lk4+1][lrow+64] = f2tf(nb1.y);
        Bs[nb][lk4+2][lrow+64] = f2tf(nb1.z); Bs[nb][lk4+3][lrow+64] = f2tf(nb1.w);
        __syncthreads();
        buf = nb;
    }

    // epilogue
    #pragma unroll
    for (int mi = 0; mi < 4; mi++) {
        #pragma unroll
        for (int half = 0; half < 2; half++) {
            int row = bm * 128 + warpM + mi * 16 + r + half * 8;
            int orow = row;
            if (EPI == 2) orow = remap_row(row);
            const float* rr = (EPI == 2 || EPI == 3) ? res + (size_t)orow * N : nullptr;
            float* cp = C + (size_t)orow * N;
            #pragma unroll
            for (int ni = 0; ni < 4; ni++) {
                int col = bn * 128 + warpN + ni * 8 + 2 * c;
                float v0 = acc[mi][ni][half * 2 + 0] + bias[col];
                float v1 = acc[mi][ni][half * 2 + 1] + bias[col + 1];
                if (EPI == 1) {
                    v0 = 0.5f * v0 * (1.0f + erff(v0 * 0.70710678118654752f));
                    v1 = 0.5f * v1 * (1.0f + erff(v1 * 0.70710678118654752f));
                }
                if (EPI == 2 || EPI == 3) {
                    v0 += rr[col];
                    v1 += rr[col + 1];
                }
                *(float2*)(cp + col) = make_float2(v0, v1);
            }
        }
    }
}

// ---------------- windowed attention -----------------------------------------
__global__ void __launch_bounds__(256) attn_kernel(const float* __restrict__ qkv,
                                                   const float* __restrict__ rpb,
                                                   const int* __restrict__ rel_idx,
                                                   const float* __restrict__ mask,
                                                   float* __restrict__ out) {
    int wwin = blockIdx.x;
    int head = blockIdx.y;
    __shared__ float qs[NTOK * 33];
    __shared__ float ks[NTOK * 33];
    __shared__ float vs[NTOK * 33];
    __shared__ float bm[NTOK * 50];
    __shared__ float pr[8][64];

    int tid = threadIdx.x;
    const float* base = qkv + (size_t)wwin * NTOK * (3 * DIM) + head * HEAD_DIM;
    for (int idx = tid; idx < NTOK * 32; idx += 256) {
        int n = idx >> 5, d = idx & 31;
        const float* rowp = base + (size_t)n * (3 * DIM);
        qs[n * 33 + d] = rowp[d];
        ks[n * 33 + d] = rowp[DIM + d];
        vs[n * 33 + d] = rowp[2 * DIM + d];
    }
    const float* mk = mask + (size_t)(wwin & 63) * (NTOK * NTOK);
    for (int idx = tid; idx < NTOK * NTOK; idx += 256) {
        int n = idx / NTOK, mcol = idx - n * NTOK;
        bm[n * 50 + mcol] = rpb[rel_idx[idx] * HEADS + head] + mk[idx];
    }
    __syncthreads();

    int warp = tid >> 5, lane = tid & 31;
    const float scale = 0.17677669529663687f;

    for (int n = warp; n < NTOK; n += 8) {
        int m0 = lane, m1 = lane + 32;
        int m1c = (m1 < NTOK) ? m1 : (NTOK - 1);
        float a0 = 0.0f, a1 = 0.0f;
        #pragma unroll
        for (int d = 0; d < 32; d++) {
            float qd = qs[n * 33 + d];
            a0 += qd * ks[m0 * 33 + d];
            a1 += qd * ks[m1c * 33 + d];
        }
        float s0 = a0 * scale + bm[n * 50 + m0];
        float s1 = (m1 < NTOK) ? (a1 * scale + bm[n * 50 + m1]) : -1e30f;
        float mx = fmaxf(s0, s1);
        #pragma unroll
        for (int o = 16; o; o >>= 1) mx = fmaxf(mx, __shfl_xor_sync(0xffffffffu, mx, o));
        float e0 = expf(s0 - mx);
        float e1 = (m1 < NTOK) ? expf(s1 - mx) : 0.0f;
        float sm = e0 + e1;
        #pragma unroll
        for (int o = 16; o; o >>= 1) sm += __shfl_xor_sync(0xffffffffu, sm, o);
        float inv = 1.0f / sm;
        pr[warp][m0] = e0 * inv;
        if (m1 < NTOK) pr[warp][m1] = e1 * inv;
        __syncwarp();
        float acc = 0.0f;
        #pragma unroll
        for (int m = 0; m < NTOK; m++) acc += pr[warp][m] * vs[m * 33 + lane];
        out[((size_t)wwin * NTOK + n) * DIM + head * HEAD_DIM + lane] = acc;
        __syncwarp();
    }
}

// ---------------- launcher ---------------------------------------------------
extern "C" void kernel_launch(void* const* d_in, const int* in_sizes, int n_in,
                              void* d_out, int out_size) {
    const float* x     = (const float*)d_in[0];
    const float* n1w   = (const float*)d_in[1];
    const float* n1b   = (const float*)d_in[2];
    const float* qkvw  = (const float*)d_in[3];
    const float* qkvb  = (const float*)d_in[4];
    const float* rpb   = (const float*)d_in[5];
    const float* projw = (const float*)d_in[6];
    const float* projb = (const float*)d_in[7];
    const float* n2w   = (const float*)d_in[8];
    const float* n2b   = (const float*)d_in[9];
    const float* fc1w  = (const float*)d_in[10];
    const float* fc1b  = (const float*)d_in[11];
    const float* fc2w  = (const float*)d_in[12];
    const float* fc2b  = (const float*)d_in[13];
    const int*   relix = (const int*)d_in[14];
    const float* amask = (const float*)d_in[15];
    float* out = (float*)d_out;

    float *hwin, *qkv, *attn, *x1, *h2;
    cudaGetSymbolAddress((void**)&hwin, g_hwin);
    cudaGetSymbolAddress((void**)&qkv,  g_qkv);
    cudaGetSymbolAddress((void**)&attn, g_attn);
    cudaGetSymbolAddress((void**)&x1,   g_x1);
    cudaGetSymbolAddress((void**)&h2,   g_h2);

    // 1. LN1 + shift + window-partition
    ln_kernel<true><<<MTOT / 8, 256>>>(x, n1w, n1b, hwin);
    // 2. QKV GEMM
    tgemm_nt<0><<<dim3(3 * DIM / 128, MTOT / 128), 256>>>(hwin, qkvw, qkvb, qkv,
                                                          MTOT, 3 * DIM, DIM, nullptr);
    // 3. windowed attention
    attn_kernel<<<dim3(BZ * NWIN, HEADS), 256>>>(qkv, rpb, relix, amask, attn);
    // 4. proj GEMM + window-reverse scatter + residual
    tgemm_nt<2><<<dim3(DIM / 128, MTOT / 128), 256>>>(attn, projw, projb, x1,
                                                      MTOT, DIM, DIM, x);
    // 5. LN2
    ln_kernel<false><<<MTOT / 8, 256>>>(x1, n2w, n2b, hwin);
    // 6. FC1 + GELU
    tgemm_nt<1><<<dim3(HIDDEN / 128, MTOT / 128), 256>>>(hwin, fc1w, fc1b, h2,
                                                         MTOT, HIDDEN, DIM, nullptr);
    // 7. FC2 + residual -> out
    tgemm_nt<3><<<dim3(DIM / 128, MTOT / 128), 256>>>(h2, fc2w, fc2b, out,
                                                      MTOT, DIM, HIDDEN, x1);
}

// round 3
// speedup vs baseline: 2.9001x; 2.1079x over previous
#include <cuda_runtime.h>
#include <cuda_bf16.h>
#include <math.h>
#include <stdint.h>

#define BZ 32
#define HH 56
#define WW 56
#define DIM 256
#define HEADS 8
#define WS 7
#define SHIFT 3
#define NTOK 49
#define NWIN 64
#define HEAD_DIM 32
#define HIDDEN 1024
#define MTOT (BZ*HH*WW)    // 100352 rows

typedef __nv_bfloat16 bf16;

// ---------------- scratch ----------------------------------------------------
__device__ bf16  g_hwin[(size_t)MTOT * DIM];       // LN out (bf16), reused for LN2
__device__ float g_qkv [(size_t)MTOT * 3 * DIM];   // qkv fp32 (attention consumes)
__device__ bf16  g_attn[(size_t)MTOT * DIM];       // attention out (bf16)
__device__ float g_x1  [(size_t)MTOT * DIM];       // x + proj (fp32)
__device__ bf16  g_h2  [(size_t)MTOT * HIDDEN];    // gelu(fc1) (bf16)
__device__ bf16  g_wqkv[3 * DIM * DIM];
__device__ bf16  g_wproj[DIM * DIM];
__device__ bf16  g_wfc1[HIDDEN * DIM];
__device__ bf16  g_wfc2[DIM * HIDDEN];

__device__ __forceinline__ int remap_row(int m) {
    int b    = m / (NWIN * NTOK);
    int rem  = m - b * (NWIN * NTOK);
    int wimg = rem / NTOK;
    int n    = rem - wimg * NTOK;
    int hh = (wimg >> 3) * WS + n / WS + SHIFT; if (hh >= HH) hh -= HH;
    int ww = (wimg & 7) * WS + n % WS + SHIFT;  if (ww >= WW) ww -= WW;
    return b * (HH * WW) + hh * WW + ww;
}

// ---------------- ptx helpers -------------------------------------------------
__device__ __forceinline__ uint32_t smem_u32(const void* p) {
    return (uint32_t)__cvta_generic_to_shared(p);
}
__device__ __forceinline__ void cp16(uint32_t dst, const void* src) {
    asm volatile("cp.async.cg.shared.global [%0], [%1], 16;\n" :: "r"(dst), "l"(src));
}
__device__ __forceinline__ void cp_commit() { asm volatile("cp.async.commit_group;\n"); }
template<int N> __device__ __forceinline__ void cp_wait() {
    asm volatile("cp.async.wait_group %0;\n" :: "n"(N));
}
__device__ __forceinline__ void ldsm4(uint32_t& r0, uint32_t& r1, uint32_t& r2, uint32_t& r3,
                                      uint32_t addr) {
    asm volatile("ldmatrix.sync.aligned.m8n8.x4.shared.b16 {%0,%1,%2,%3}, [%4];"
                 : "=r"(r0), "=r"(r1), "=r"(r2), "=r"(r3) : "r"(addr));
}
__device__ __forceinline__ void mma_bf16(float* d, const uint32_t* a, const uint32_t* b) {
    asm volatile(
        "mma.sync.aligned.m16n8k16.row.col.f32.bf16.bf16.f32 "
        "{%0,%1,%2,%3}, {%4,%5,%6,%7}, {%8,%9}, {%0,%1,%2,%3};\n"
        : "+f"(d[0]), "+f"(d[1]), "+f"(d[2]), "+f"(d[3])
        : "r"(a[0]), "r"(a[1]), "r"(a[2]), "r"(a[3]), "r"(b[0]), "r"(b[1]));
}

// ---------------- fp32 -> bf16 weight convert --------------------------------
__global__ void cvt_kernel(const float* __restrict__ src, bf16* __restrict__ dst, int n) {
    int i = (blockIdx.x * blockDim.x + threadIdx.x) * 4;
    if (i < n) {
        float4 v = *(const float4*)(src + i);
        __nv_bfloat162 p0 = {__float2bfloat16(v.x), __float2bfloat16(v.y)};
        __nv_bfloat162 p1 = {__float2bfloat16(v.z), __float2bfloat16(v.w)};
        *(__nv_bfloat162*)(dst + i)     = p0;
        *(__nv_bfloat162*)(dst + i + 2) = p1;
    }
}

// ---------------- LayerNorm (warp per row, bf16 out) -------------------------
template<bool SHIFTMAP>
__global__ void __launch_bounds__(256) ln_kernel(const float* __restrict__ x,
                                                 const float* __restrict__ gw,
                                                 const float* __restrict__ gb,
                                                 bf16* __restrict__ out) {
    int warp = threadIdx.x >> 5, lane = threadIdx.x & 31;
    int m = blockIdx.x * 8 + warp;
    const float* xr;
    if (SHIFTMAP) {
        int r = remap_row(m);
        xr = x + (size_t)r * DIM;
    } else {
        xr = x + (size_t)m * DIM;
    }
    float4 v0 = *(const float4*)(xr + lane * 4);
    float4 v1 = *(const float4*)(xr + 128 + lane * 4);
    float s  = v0.x + v0.y + v0.z + v0.w + v1.x + v1.y + v1.z + v1.w;
    float sq = v0.x*v0.x + v0.y*v0.y + v0.z*v0.z + v0.w*v0.w
             + v1.x*v1.x + v1.y*v1.y + v1.z*v1.z + v1.w*v1.w;
    #pragma unroll
    for (int o = 16; o; o >>= 1) {
        s  += __shfl_xor_sync(0xffffffffu, s,  o);
        sq += __shfl_xor_sync(0xffffffffu, sq, o);
    }
    float mu  = s * (1.0f / DIM);
    float var = sq * (1.0f / DIM) - mu * mu;
    float rs  = rsqrtf(var + 1e-5f);
    float4 w0 = *(const float4*)(gw + lane * 4);
    float4 w1 = *(const float4*)(gw + 128 + lane * 4);
    float4 b0 = *(const float4*)(gb + lane * 4);
    float4 b1 = *(const float4*)(gb + 128 + lane * 4);
    bf16* orow = out + (size_t)m * DIM;
    __nv_bfloat162 p;
    p = {__float2bfloat16((v0.x-mu)*rs*w0.x+b0.x), __float2bfloat16((v0.y-mu)*rs*w0.y+b0.y)};
    *(__nv_bfloat162*)(orow + lane*4)     = p;
    p = {__float2bfloat16((v0.z-mu)*rs*w0.z+b0.z), __float2bfloat16((v0.w-mu)*rs*w0.w+b0.w)};
    *(__nv_bfloat162*)(orow + lane*4 + 2) = p;
    p = {__float2bfloat16((v1.x-mu)*rs*w1.x+b1.x), __float2bfloat16((v1.y-mu)*rs*w1.y+b1.y)};
    *(__nv_bfloat162*)(orow + 128 + lane*4)     = p;
    p = {__float2bfloat16((v1.z-mu)*rs*w1.z+b1.z), __float2bfloat16((v1.w-mu)*rs*w1.w+b1.w)};
    *(__nv_bfloat162*)(orow + 128 + lane*4 + 2) = p;
}

// ---------------- bf16 tensor-core GEMM (NT) ---------------------------------
// A[M,K] bf16 row-major, B[N,K] bf16 row-major. 128x128 tile, BK=32, 256 thr.
// Warp grid 2(m) x 4(n); warp tile 64x32 = 4x4 m16n8k16 fragments.
// smem rows padded to 40 bf16 (80B) -> conflict-free ldmatrix.
// EPI: 0=+bias->f32  1=+bias,GELU->bf16  2=+bias,remap,+res->f32  3=+bias,+res->f32
#define SROW 80              // bytes per smem row
#define TILEB 10240          // 128 * 80
template<int EPI>
__global__ void __launch_bounds__(256, 2) bgemm_nt(const bf16* __restrict__ A,
                                                  const bf16* __restrict__ Bm,
                                                  const float* __restrict__ bias,
                                                  void* __restrict__ Cv,
                                                  int M, int N, int K,
                                                  const float* __restrict__ res) {
    __shared__ __align__(16) char smem[4 * TILEB];   // A0 A1 B0 B1
    uint32_t sbase = smem_u32(smem);
    int tid = threadIdx.x;
    int bn = blockIdx.x, bm = blockIdx.y;
    int warp = tid >> 5, lane = tid & 31;
    int warpM = (warp & 1) * 64;
    int warpN = (warp >> 1) * 32;
    int r = lane >> 2, c = lane & 3;

    // gmem source pointers for this thread (row = tid>>1, two 16B chunks)
    int lrow = tid >> 1;
    int lch  = (tid & 1) * 16;        // elem offset of first chunk
    const bf16* Ag = A  + (size_t)(bm * 128 + lrow) * K + lch;
    const bf16* Bg = Bm + (size_t)(bn * 128 + lrow) * K + lch;
    uint32_t adst = sbase + lrow * SROW + (tid & 1) * 32;
    uint32_t bdst = adst + 2 * TILEB;

    // ldmatrix per-lane offsets
    uint32_t aoff = (uint32_t)((lane & 15) * SROW + (lane >> 4) * 16);
    uint32_t boff = (uint32_t)(((lane & 7) + ((lane >> 4) << 3)) * SROW + ((lane & 8) ? 16 : 0));

    float acc[4][4][4];
    #pragma unroll
    for (int mi = 0; mi < 4; mi++)
        #pragma unroll
        for (int ni = 0; ni < 4; ni++)
            #pragma unroll
            for (int t = 0; t < 4; t++) acc[mi][ni][t] = 0.0f;

    int nk = K >> 5;
    // prologue: stages 0,1
    #pragma unroll
    for (int s = 0; s < 2; s++) {
        cp16(adst + s * TILEB,      Ag);
        cp16(adst + s * TILEB + 16, Ag + 8);
        cp16(bdst + s * TILEB,      Bg);
        cp16(bdst + s * TILEB + 16, Bg + 8);
        Ag += 32; Bg += 32;
        cp_commit();
    }

    for (int i = 0; i < nk; i++) {
        cp_wait<1>();
        __syncthreads();
        int buf = i & 1;
        uint32_t Ab = sbase + buf * TILEB;
        uint32_t Bb = sbase + (2 + buf) * TILEB;
        #pragma unroll
        for (int kk = 0; kk < 2; kk++) {
            uint32_t af[4][4], bfr[2][4];
            #pragma unroll
            for (int mi = 0; mi < 4; mi++)
                ldsm4(af[mi][0], af[mi][1], af[mi][2], af[mi][3],
                      Ab + (uint32_t)((warpM + mi * 16) * SROW + kk * 32) + aoff);
            #pragma unroll
            for (int p = 0; p < 2; p++)
                ldsm4(bfr[p][0], bfr[p][1], bfr[p][2], bfr[p][3],
                      Bb + (uint32_t)((warpN + p * 16) * SROW + kk * 32) + boff);
            #pragma unroll
            for (int mi = 0; mi < 4; mi++)
                #pragma unroll
                for (int ni = 0; ni < 4; ni++)
                    mma_bf16(acc[mi][ni], af[mi], &bfr[ni >> 1][(ni & 1) * 2]);
        }
        __syncthreads();
        if (i + 2 < nk) {
            cp16(adst + buf * TILEB,      Ag);
            cp16(adst + buf * TILEB + 16, Ag + 8);
            cp16(bdst + buf * TILEB,      Bg);
            cp16(bdst + buf * TILEB + 16, Bg + 8);
            Ag += 32; Bg += 32;
        }
        cp_commit();
    }

    // epilogue
    #pragma unroll
    for (int mi = 0; mi < 4; mi++) {
        #pragma unroll
        for (int half = 0; half < 2; half++) {
            int row = bm * 128 + warpM + mi * 16 + r + half * 8;
            int orow = row;
            if (EPI == 2) orow = remap_row(row);
            const float* rr = (EPI == 2 || EPI == 3) ? res + (size_t)orow * N : nullptr;
            #pragma unroll
            for (int ni = 0; ni < 4; ni++) {
                int col = bn * 128 + warpN + ni * 8 + 2 * c;
                float v0 = acc[mi][ni][half * 2 + 0] + bias[col];
                float v1 = acc[mi][ni][half * 2 + 1] + bias[col + 1];
                if (EPI == 1) {
                    v0 = 0.5f * v0 * (1.0f + erff(v0 * 0.70710678118654752f));
                    v1 = 0.5f * v1 * (1.0f + erff(v1 * 0.70710678118654752f));
                }
                if (EPI == 2 || EPI == 3) {
                    v0 += rr[col];
                    v1 += rr[col + 1];
                }
                if (EPI == 1) {
                    bf16* cp = (bf16*)Cv + (size_t)orow * N;
                    __nv_bfloat162 pk = {__float2bfloat16(v0), __float2bfloat16(v1)};
                    *(__nv_bfloat162*)(cp + col) = pk;
                } else {
                    float* cp = (float*)Cv + (size_t)orow * N;
                    *(float2*)(cp + col) = make_float2(v0, v1);
                }
            }
        }
    }
}

// ---------------- windowed attention (fp32 in, bf16 out) ---------------------
__global__ void __launch_bounds__(256) attn_kernel(const float* __restrict__ qkv,
                                                   const float* __restrict__ rpb,
                                                   const int* __restrict__ rel_idx,
                                                   const float* __restrict__ mask,
                                                   bf16* __restrict__ out) {
    int wwin = blockIdx.x;
    int head = blockIdx.y;
    __shared__ float qs[NTOK * 33];
    __shared__ float ks[NTOK * 33];
    __shared__ float vs[NTOK * 33];
    __shared__ float bm[NTOK * 50];
    __shared__ float pr[8][64];

    int tid = threadIdx.x;
    const float* base = qkv + (size_t)wwin * NTOK * (3 * DIM) + head * HEAD_DIM;
    for (int idx = tid; idx < NTOK * 32; idx += 256) {
        int n = idx >> 5, d = idx & 31;
        const float* rowp = base + (size_t)n * (3 * DIM);
        qs[n * 33 + d] = rowp[d];
        ks[n * 33 + d] = rowp[DIM + d];
        vs[n * 33 + d] = rowp[2 * DIM + d];
    }
    const float* mk = mask + (size_t)(wwin & 63) * (NTOK * NTOK);
    for (int idx = tid; idx < NTOK * NTOK; idx += 256) {
        int n = idx / NTOK, mcol = idx - n * NTOK;
        bm[n * 50 + mcol] = rpb[rel_idx[idx] * HEADS + head] + mk[idx];
    }
    __syncthreads();

    int warp = tid >> 5, lane = tid & 31;
    const float scale = 0.17677669529663687f;

    for (int n = warp; n < NTOK; n += 8) {
        int m0 = lane, m1 = lane + 32;
        int m1c = (m1 < NTOK) ? m1 : (NTOK - 1);
        float a0 = 0.0f, a1 = 0.0f;
        #pragma unroll
        for (int d = 0; d < 32; d++) {
            float qd = qs[n * 33 + d];
            a0 += qd * ks[m0 * 33 + d];
            a1 += qd * ks[m1c * 33 + d];
        }
        float s0 = a0 * scale + bm[n * 50 + m0];
        float s1 = (m1 < NTOK) ? (a1 * scale + bm[n * 50 + m1]) : -1e30f;
        float mx = fmaxf(s0, s1);
        #pragma unroll
        for (int o = 16; o; o >>= 1) mx = fmaxf(mx, __shfl_xor_sync(0xffffffffu, mx, o));
        float e0 = expf(s0 - mx);
        float e1 = (m1 < NTOK) ? expf(s1 - mx) : 0.0f;
        float sm = e0 + e1;
        #pragma unroll
        for (int o = 16; o; o >>= 1) sm += __shfl_xor_sync(0xffffffffu, sm, o);
        float inv = 1.0f / sm;
        pr[warp][m0] = e0 * inv;
        if (m1 < NTOK) pr[warp][m1] = e1 * inv;
        __syncwarp();
        float acc = 0.0f;
        #pragma unroll
        for (int m = 0; m < NTOK; m++) acc += pr[warp][m] * vs[m * 33 + lane];
        out[((size_t)wwin * NTOK + n) * DIM + head * HEAD_DIM + lane] = __float2bfloat16(acc);
        __syncwarp();
    }
}

// ---------------- launcher ---------------------------------------------------
extern "C" void kernel_launch(void* const* d_in, const int* in_sizes, int n_in,
                              void* d_out, int out_size) {
    const float* x     = (const float*)d_in[0];
    const float* n1w   = (const float*)d_in[1];
    const float* n1b   = (const float*)d_in[2];
    const float* qkvw  = (const float*)d_in[3];
    const float* qkvb  = (const float*)d_in[4];
    const float* rpb   = (const float*)d_in[5];
    const float* projw = (const float*)d_in[6];
    const float* projb = (const float*)d_in[7];
    const float* n2w   = (const float*)d_in[8];
    const float* n2b   = (const float*)d_in[9];
    const float* fc1w  = (const float*)d_in[10];
    const float* fc1b  = (const float*)d_in[11];
    const float* fc2w  = (const float*)d_in[12];
    const float* fc2b  = (const float*)d_in[13];
    const int*   relix = (const int*)d_in[14];
    const float* amask = (const float*)d_in[15];
    float* out = (float*)d_out;

    bf16 *hwin, *attn, *h2, *wqkv, *wproj, *wfc1, *wfc2;
    float *qkv, *x1;
    cudaGetSymbolAddress((void**)&hwin, g_hwin);
    cudaGetSymbolAddress((void**)&qkv,  g_qkv);
    cudaGetSymbolAddress((void**)&attn, g_attn);
    cudaGetSymbolAddress((void**)&x1,   g_x1);
    cudaGetSymbolAddress((void**)&h2,   g_h2);
    cudaGetSymbolAddress((void**)&wqkv, g_wqkv);
    cudaGetSymbolAddress((void**)&wproj, g_wproj);
    cudaGetSymbolAddress((void**)&wfc1, g_wfc1);
    cudaGetSymbolAddress((void**)&wfc2, g_wfc2);

    // weight conversion (cheap, every launch for determinism)
    cvt_kernel<<<(3*DIM*DIM/4 + 255)/256, 256>>>(qkvw, wqkv, 3*DIM*DIM);
    cvt_kernel<<<(DIM*DIM/4 + 255)/256, 256>>>(projw, wproj, DIM*DIM);
    cvt_kernel<<<(HIDDEN*DIM/4 + 255)/256, 256>>>(fc1w, wfc1, HIDDEN*DIM);
    cvt_kernel<<<(DIM*HIDDEN/4 + 255)/256, 256>>>(fc2w, wfc2, DIM*HIDDEN);

    // 1. LN1 + shift + window-partition (bf16 out)
    ln_kernel<true><<<MTOT / 8, 256>>>(x, n1w, n1b, hwin);
    // 2. QKV GEMM (bf16 x bf16 -> f32)
    bgemm_nt<0><<<dim3(3 * DIM / 128, MTOT / 128), 256>>>(hwin, wqkv, qkvb, qkv,
                                                          MTOT, 3 * DIM, DIM, nullptr);
    // 3. windowed attention
    attn_kernel<<<dim3(BZ * NWIN, HEADS), 256>>>(qkv, rpb, relix, amask, attn);
    // 4. proj GEMM + window-reverse scatter + residual
    bgemm_nt<2><<<dim3(DIM / 128, MTOT / 128), 256>>>(attn, wproj, projb, x1,
                                                      MTOT, DIM, DIM, x);
    // 5. LN2 (bf16 out)
    ln_kernel<false><<<MTOT / 8, 256>>>(x1, n2w, n2b, hwin);
    // 6. FC1 + GELU (bf16 out)
    bgemm_nt<1><<<dim3(HIDDEN / 128, MTOT / 128), 256>>>(hwin, wfc1, fc1b, h2,
                                                         MTOT, HIDDEN, DIM, nullptr);
    // 7. FC2 + residual -> out
    bgemm_nt<3><<<dim3(DIM / 128, MTOT / 128), 256>>>(h2, wfc2, fc2b, out,
                                                      MTOT, DIM, HIDDEN, x1);
}

// round 6
// speedup vs baseline: 2.9354x; 1.0122x over previous
#include <cuda_runtime.h>
#include <cuda_bf16.h>
#include <math.h>
#include <stdint.h>

#define BZ 32
#define HH 56
#define WW 56
#define DIM 256
#define HEADS 8
#define WS 7
#define SHIFT 3
#define NTOK 49
#define NWIN 64
#define HEAD_DIM 32
#define HIDDEN 1024
#define MTOT (BZ*HH*WW)    // 100352 rows

typedef __nv_bfloat16 bf16;

// ---------------- scratch ----------------------------------------------------
__device__ bf16  g_hwin[(size_t)MTOT * DIM];
__device__ bf16  g_qkv [(size_t)MTOT * 3 * DIM];
__device__ bf16  g_attn[(size_t)MTOT * DIM];
__device__ float g_x1  [(size_t)MTOT * DIM];
__device__ bf16  g_h2  [(size_t)MTOT * HIDDEN];
__device__ bf16  g_wqkv[3 * DIM * DIM];
__device__ bf16  g_wproj[DIM * DIM];
__device__ bf16  g_wfc1[HIDDEN * DIM];
__device__ bf16  g_wfc2[DIM * HIDDEN];

__device__ __forceinline__ int remap_row(int m) {
    int b    = m / (NWIN * NTOK);
    int rem  = m - b * (NWIN * NTOK);
    int wimg = rem / NTOK;
    int n    = rem - wimg * NTOK;
    int hh = (wimg >> 3) * WS + n / WS + SHIFT; if (hh >= HH) hh -= HH;
    int ww = (wimg & 7) * WS + n % WS + SHIFT;  if (ww >= WW) ww -= WW;
    return b * (HH * WW) + hh * WW + ww;
}

// ---------------- ptx helpers -------------------------------------------------
__device__ __forceinline__ uint32_t smem_u32(const void* p) {
    return (uint32_t)__cvta_generic_to_shared(p);
}
__device__ __forceinline__ void cp16(uint32_t dst, const void* src) {
    asm volatile("cp.async.cg.shared.global [%0], [%1], 16;\n" :: "r"(dst), "l"(src));
}
__device__ __forceinline__ void cp_commit() { asm volatile("cp.async.commit_group;\n"); }
template<int N> __device__ __forceinline__ void cp_wait() {
    asm volatile("cp.async.wait_group %0;\n" :: "n"(N));
}
__device__ __forceinline__ void ldsm4(uint32_t* r, uint32_t addr) {
    asm volatile("ldmatrix.sync.aligned.m8n8.x4.shared.b16 {%0,%1,%2,%3}, [%4];"
                 : "=r"(r[0]), "=r"(r[1]), "=r"(r[2]), "=r"(r[3]) : "r"(addr));
}
__device__ __forceinline__ void mma_bf16(float* d, const uint32_t* a, const uint32_t* b) {
    asm volatile(
        "mma.sync.aligned.m16n8k16.row.col.f32.bf16.bf16.f32 "
        "{%0,%1,%2,%3}, {%4,%5,%6,%7}, {%8,%9}, {%0,%1,%2,%3};\n"
        : "+f"(d[0]), "+f"(d[1]), "+f"(d[2]), "+f"(d[3])
        : "r"(a[0]), "r"(a[1]), "r"(a[2]), "r"(a[3]), "r"(b[0]), "r"(b[1]));
}

// ---------------- fp32 -> bf16 weight convert (fused, 4 segs) -----------------
__global__ void cvt4_kernel(const float* s0, bf16* d0, int n0,
                            const float* s1, bf16* d1, int n1,
                            const float* s2, bf16* d2, int n2,
                            const float* s3, bf16* d3, int n3) {
    const float* s; bf16* d; int n;
    switch (blockIdx.y) {
        case 0: s = s0; d = d0; n = n0; break;
        case 1: s = s1; d = d1; n = n1; break;
        case 2: s = s2; d = d2; n = n2; break;
        default: s = s3; d = d3; n = n3; break;
    }
    int i = (blockIdx.x * blockDim.x + threadIdx.x) * 4;
    if (i < n) {
        float4 v = *(const float4*)(s + i);
        __nv_bfloat162 p0 = {__float2bfloat16(v.x), __float2bfloat16(v.y)};
        __nv_bfloat162 p1 = {__float2bfloat16(v.z), __float2bfloat16(v.w)};
        *(__nv_bfloat162*)(d + i)     = p0;
        *(__nv_bfloat162*)(d + i + 2) = p1;
    }
}

// ---------------- LayerNorm (warp per row, bf16 out) -------------------------
template<bool SHIFTMAP>
__global__ void __launch_bounds__(256) ln_kernel(const float* __restrict__ x,
                                                 const float* __restrict__ gw,
                                                 const float* __restrict__ gb,
                                                 bf16* __restrict__ out) {
    int warp = threadIdx.x >> 5, lane = threadIdx.x & 31;
    int m = blockIdx.x * 8 + warp;
    const float* xr;
    if (SHIFTMAP) {
        int r = remap_row(m);
        xr = x + (size_t)r * DIM;
    } else {
        xr = x + (size_t)m * DIM;
    }
    float4 v0 = *(const float4*)(xr + lane * 4);
    float4 v1 = *(const float4*)(xr + 128 + lane * 4);
    float s  = v0.x + v0.y + v0.z + v0.w + v1.x + v1.y + v1.z + v1.w;
    float sq = v0.x*v0.x + v0.y*v0.y + v0.z*v0.z + v0.w*v0.w
             + v1.x*v1.x + v1.y*v1.y + v1.z*v1.z + v1.w*v1.w;
    #pragma unroll
    for (int o = 16; o; o >>= 1) {
        s  += __shfl_xor_sync(0xffffffffu, s,  o);
        sq += __shfl_xor_sync(0xffffffffu, sq, o);
    }
    float mu  = s * (1.0f / DIM);
    float var = sq * (1.0f / DIM) - mu * mu;
    float rs  = rsqrtf(var + 1e-5f);
    float4 w0 = *(const float4*)(gw + lane * 4);
    float4 w1 = *(const float4*)(gw + 128 + lane * 4);
    float4 b0 = *(const float4*)(gb + lane * 4);
    float4 b1 = *(const float4*)(gb + 128 + lane * 4);
    bf16* orow = out + (size_t)m * DIM;
    __nv_bfloat162 p;
    p = {__float2bfloat16((v0.x-mu)*rs*w0.x+b0.x), __float2bfloat16((v0.y-mu)*rs*w0.y+b0.y)};
    *(__nv_bfloat162*)(orow + lane*4)     = p;
    p = {__float2bfloat16((v0.z-mu)*rs*w0.z+b0.z), __float2bfloat16((v0.w-mu)*rs*w0.w+b0.w)};
    *(__nv_bfloat162*)(orow + lane*4 + 2) = p;
    p = {__float2bfloat16((v1.x-mu)*rs*w1.x+b1.x), __float2bfloat16((v1.y-mu)*rs*w1.y+b1.y)};
    *(__nv_bfloat162*)(orow + 128 + lane*4)     = p;
    p = {__float2bfloat16((v1.z-mu)*rs*w1.z+b1.z), __float2bfloat16((v1.w-mu)*rs*w1.w+b1.w)};
    *(__nv_bfloat162*)(orow + 128 + lane*4 + 2) = p;
}

// ---------------- bf16 mma.sync GEMM (NT), CTA 128x256, BK=32, 4-stage -------
// A[M,K] bf16 row-major, B[N,K] bf16 row-major. 8 warps, warp tile 64x64.
// smem rows padded to 80B -> conflict-free ldmatrix.
// EPI: 0=+bias->bf16  1=+bias,GELU->bf16  2=+bias,remap,+res->f32  3=+bias,+res->f32
#define SROW 80
#define ASTAGE (128 * SROW)         // 10240
#define BSTAGE (256 * SROW)         // 20480
#define STAGEB (ASTAGE + BSTAGE)    // 30720
#define NSTAGE 4
#define SMEM_DYN (NSTAGE * STAGEB)  // 122880

template<int EPI>
__global__ void __launch_bounds__(256, 1) bgemm(const bf16* __restrict__ A,
                                               const bf16* __restrict__ Bm,
                                               const float* __restrict__ bias,
                                               void* __restrict__ Cv,
                                               int M, int N, int K,
                                               const float* __restrict__ res) {
    extern __shared__ __align__(16) char smem[];
    uint32_t sbase = smem_u32(smem);
    int tid = threadIdx.x;
    int bn = blockIdx.x, bm = blockIdx.y;
    int warp = tid >> 5, lane = tid & 31;
    int warpM = (warp & 1) * 64;
    int warpN = (warp >> 1) * 64;
    int r = lane >> 2, c = lane & 3;

    // fill coords: A 512 chunks (2/thread), B 1024 chunks (4/thread)
    int arw[2], acc_[2], brw[4], bcc[4];
    #pragma unroll
    for (int rpt = 0; rpt < 2; rpt++) {
        int ch = tid + rpt * 256;
        arw[rpt] = ch >> 2; acc_[rpt] = ch & 3;
    }
    #pragma unroll
    for (int rpt = 0; rpt < 4; rpt++) {
        int ch = tid + rpt * 256;
        brw[rpt] = ch >> 2; bcc[rpt] = ch & 3;
    }
    const bf16* Abase = A  + (size_t)(bm * 128) * K;
    const bf16* Bbase = Bm + (size_t)(bn * 256) * K;

    uint32_t aoff = (uint32_t)((lane & 15) * SROW + (lane >> 4) * 16);
    uint32_t boff = (uint32_t)(((lane & 7) + ((lane >> 4) << 3)) * SROW + ((lane & 8) ? 16 : 0));

    float acc[4][8][4];
    #pragma unroll
    for (int mi = 0; mi < 4; mi++)
        #pragma unroll
        for (int ni = 0; ni < 8; ni++)
            #pragma unroll
            for (int t = 0; t < 4; t++) acc[mi][ni][t] = 0.0f;

#define FILL(s, k0) do { \
    uint32_t ab = sbase + (s) * STAGEB; \
    uint32_t bb = ab + ASTAGE; \
    _Pragma("unroll") \
    for (int rpt = 0; rpt < 2; rpt++) \
        cp16(ab + arw[rpt] * SROW + acc_[rpt] * 16, \
             Abase + (size_t)arw[rpt] * K + (k0) + acc_[rpt] * 8); \
    _Pragma("unroll") \
    for (int rpt = 0; rpt < 4; rpt++) \
        cp16(bb + brw[rpt] * SROW + bcc[rpt] * 16, \
             Bbase + (size_t)brw[rpt] * K + (k0) + bcc[rpt] * 8); \
} while (0)

    int nk = K >> 5;
    FILL(0, 0);  cp_commit();
    FILL(1, 32); cp_commit();
    FILL(2, 64); cp_commit();

    for (int i = 0; i < nk; i++) {
        cp_wait<2>();
        __syncthreads();
        int buf = i & 3;
        uint32_t Ab = sbase + buf * STAGEB;
        uint32_t Bb = Ab + ASTAGE;
        #pragma unroll
        for (int kk = 0; kk < 2; kk++) {
            uint32_t af[4][4], bfr[4][4];
            #pragma unroll
            for (int mi = 0; mi < 4; mi++)
                ldsm4(af[mi], Ab + (uint32_t)((warpM + mi * 16) * SROW + kk * 32) + aoff);
            #pragma unroll
            for (int p = 0; p < 4; p++)
                ldsm4(bfr[p], Bb + (uint32_t)((warpN + p * 16) * SROW + kk * 32) + boff);
            #pragma unroll
            for (int mi = 0; mi < 4; mi++)
                #pragma unroll
                for (int ni = 0; ni < 8; ni++)
                    mma_bf16(acc[mi][ni], af[mi], &bfr[ni >> 1][(ni & 1) * 2]);
        }
        if (i + 3 < nk) FILL((i + 3) & 3, (i + 3) * 32);
        cp_commit();
    }

    // epilogue
    #pragma unroll
    for (int mi = 0; mi < 4; mi++) {
        #pragma unroll
        for (int half = 0; half < 2; half++) {
            int row = bm * 128 + warpM + mi * 16 + r + half * 8;
            int orow = row;
            if (EPI == 2) orow = remap_row(row);
            const float* rr = (EPI == 2 || EPI == 3) ? res + (size_t)orow * N : nullptr;
            #pragma unroll
            for (int ni = 0; ni < 8; ni++) {
                int col = bn * 256 + warpN + ni * 8 + 2 * c;
                float v0 = acc[mi][ni][half * 2 + 0] + bias[col];
                float v1 = acc[mi][ni][half * 2 + 1] + bias[col + 1];
                if (EPI == 1) {
                    v0 = 0.5f * v0 * (1.0f + erff(v0 * 0.70710678118654752f));
                    v1 = 0.5f * v1 * (1.0f + erff(v1 * 0.70710678118654752f));
                }
                if (EPI == 2 || EPI == 3) {
                    v0 += rr[col];
                    v1 += rr[col + 1];
                }
                if (EPI == 0 || EPI == 1) {
                    bf16* cp = (bf16*)Cv + (size_t)orow * N;
                    __nv_bfloat162 pk = {__float2bfloat16(v0), __float2bfloat16(v1)};
                    *(__nv_bfloat162*)(cp + col) = pk;
                } else {
                    float* cp = (float*)Cv + (size_t)orow * N;
                    *(float2*)(cp + col) = make_float2(v0, v1);
                }
            }
        }
    }
#undef FILL
}

// ---------------- windowed attention (bf16 in, bf16 out) ---------------------
__global__ void __launch_bounds__(256) attn_kernel(const bf16* __restrict__ qkv,
                                                   const float* __restrict__ rpb,
                                                   const int* __restrict__ rel_idx,
                                                   const float* __restrict__ mask,
                                                   bf16* __restrict__ out) {
    int wwin = blockIdx.x;
    int head = blockIdx.y;
    __shared__ float qs[NTOK * 33];
    __shared__ float ks[NTOK * 33];
    __shared__ float vs[NTOK * 33];
    __shared__ float bm[NTOK * 50];
    __shared__ float pr[8][64];

    int tid = threadIdx.x;
    const bf16* base = qkv + (size_t)wwin * NTOK * (3 * DIM) + head * HEAD_DIM;
    for (int idx = tid; idx < NTOK * 16; idx += 256) {
        int n = idx >> 4, d2 = (idx & 15) * 2;
        const bf16* rowp = base + (size_t)n * (3 * DIM);
        __nv_bfloat162 q2 = *(const __nv_bfloat162*)(rowp + d2);
        __nv_bfloat162 k2 = *(const __nv_bfloat162*)(rowp + DIM + d2);
        __nv_bfloat162 v2 = *(const __nv_bfloat162*)(rowp + 2 * DIM + d2);
        qs[n * 33 + d2] = __bfloat162float(q2.x); qs[n * 33 + d2 + 1] = __bfloat162float(q2.y);
        ks[n * 33 + d2] = __bfloat162float(k2.x); ks[n * 33 + d2 + 1] = __bfloat162float(k2.y);
        vs[n * 33 + d2] = __bfloat162float(v2.x); vs[n * 33 + d2 + 1] = __bfloat162float(v2.y);
    }
    const float* mk = mask + (size_t)(wwin & 63) * (NTOK * NTOK);
    for (int idx = tid; idx < NTOK * NTOK; idx += 256) {
        int n = idx / NTOK, mcol = idx - n * NTOK;
        bm[n * 50 + mcol] = rpb[rel_idx[idx] * HEADS + head] + mk[idx];
    }
    __syncthreads();

    int warp = tid >> 5, lane = tid & 31;
    const float scale = 0.17677669529663687f;

    for (int n = warp; n < NTOK; n += 8) {
        int m0 = lane, m1 = lane + 32;
        int m1c = (m1 < NTOK) ? m1 : (NTOK - 1);
        float a0 = 0.0f, a1 = 0.0f;
        #pragma unroll
        for (int d = 0; d < 32; d++) {
            float qd = qs[n * 33 + d];
            a0 += qd * ks[m0 * 33 + d];
            a1 += qd * ks[m1c * 33 + d];
        }
        float s0 = a0 * scale + bm[n * 50 + m0];
        float s1 = (m1 < NTOK) ? (a1 * scale + bm[n * 50 + m1]) : -1e30f;
        float mx = fmaxf(s0, s1);
        #pragma unroll
        for (int o = 16; o; o >>= 1) mx = fmaxf(mx, __shfl_xor_sync(0xffffffffu, mx, o));
        float e0 = expf(s0 - mx);
        float e1 = (m1 < NTOK) ? expf(s1 - mx) : 0.0f;
        float sm = e0 + e1;
        #pragma unroll
        for (int o = 16; o; o >>= 1) sm += __shfl_xor_sync(0xffffffffu, sm, o);
        float inv = 1.0f / sm;
        pr[warp][m0] = e0 * inv;
        if (m1 < NTOK) pr[warp][m1] = e1 * inv;
        __syncwarp();
        float acc = 0.0f;
        #pragma unroll
        for (int m = 0; m < NTOK; m++) acc += pr[warp][m] * vs[m * 33 + lane];
        out[((size_t)wwin * NTOK + n) * DIM + head * HEAD_DIM + lane] = __float2bfloat16(acc);
        __syncwarp();
    }
}

// ---------------- launcher ---------------------------------------------------
extern "C" void kernel_launch(void* const* d_in, const int* in_sizes, int n_in,
                              void* d_out, int out_size) {
    const float* x     = (const float*)d_in[0];
    const float* n1w   = (const float*)d_in[1];
    const float* n1b   = (const float*)d_in[2];
    const float* qkvw  = (const float*)d_in[3];
    const float* qkvb  = (const float*)d_in[4];
    const float* rpb   = (const float*)d_in[5];
    const float* projw = (const float*)d_in[6];
    const float* projb = (const float*)d_in[7];
    const float* n2w   = (const float*)d_in[8];
    const float* n2b   = (const float*)d_in[9];
    const float* fc1w  = (const float*)d_in[10];
    const float* fc1b  = (const float*)d_in[11];
    const float* fc2w  = (const float*)d_in[12];
    const float* fc2b  = (const float*)d_in[13];
    const int*   relix = (const int*)d_in[14];
    const float* amask = (const float*)d_in[15];
    float* out = (float*)d_out;

    bf16 *hwin, *qkv, *attn, *h2, *wqkv, *wproj, *wfc1, *wfc2;
    float *x1;
    cudaGetSymbolAddress((void**)&hwin, g_hwin);
    cudaGetSymbolAddress((void**)&qkv,  g_qkv);
    cudaGetSymbolAddress((void**)&attn, g_attn);
    cudaGetSymbolAddress((void**)&x1,   g_x1);
    cudaGetSymbolAddress((void**)&h2,   g_h2);
    cudaGetSymbolAddress((void**)&wqkv, g_wqkv);
    cudaGetSymbolAddress((void**)&wproj, g_wproj);
    cudaGetSymbolAddress((void**)&wfc1, g_wfc1);
    cudaGetSymbolAddress((void**)&wfc2, g_wfc2);

    // set attributes unconditionally (no static guards allowed)
    cudaFuncSetAttribute(bgemm<0>, cudaFuncAttributeMaxDynamicSharedMemorySize, SMEM_DYN);
    cudaFuncSetAttribute(bgemm<1>, cudaFuncAttributeMaxDynamicSharedMemorySize, SMEM_DYN);
    cudaFuncSetAttribute(bgemm<2>, cudaFuncAttributeMaxDynamicSharedMemorySize, SMEM_DYN);
    cudaFuncSetAttribute(bgemm<3>, cudaFuncAttributeMaxDynamicSharedMemorySize, SMEM_DYN);

    // weight conversion (one fused launch)
    cvt4_kernel<<<dim3(DIM * HIDDEN / 4 / 256, 4), 256>>>(
        qkvw, wqkv, 3 * DIM * DIM,
        projw, wproj, DIM * DIM,
        fc1w, wfc1, HIDDEN * DIM,
        fc2w, wfc2, DIM * HIDDEN);

    // 1. LN1 + shift + window-partition (bf16 out)
    ln_kernel<true><<<MTOT / 8, 256>>>(x, n1w, n1b, hwin);
    // 2. QKV GEMM -> bf16
    bgemm<0><<<dim3(3, MTOT / 128), 256, SMEM_DYN>>>(hwin, wqkv, qkvb, qkv,
                                                     MTOT, 3 * DIM, DIM, nullptr);
    // 3. windowed attention
    attn_kernel<<<dim3(BZ * NWIN, HEADS), 256>>>(qkv, rpb, relix, amask, attn);
    // 4. proj GEMM + window-reverse scatter + residual -> f32
    bgemm<2><<<dim3(1, MTOT / 128), 256, SMEM_DYN>>>(attn, wproj, projb, x1,
                                                     MTOT, DIM, DIM, x);
    // 5. LN2 (bf16 out)
    ln_kernel<false><<<MTOT / 8, 256>>>(x1, n2w, n2b, hwin);
    // 6. FC1 + GELU -> bf16
    bgemm<1><<<dim3(4, MTOT / 128), 256, SMEM_DYN>>>(hwin, wfc1, fc1b, h2,
                                                     MTOT, HIDDEN, DIM, nullptr);
    // 7. FC2 + residual -> out (f32)
    bgemm<3><<<dim3(1, MTOT / 128), 256, SMEM_DYN>>>(h2, wfc2, fc2b, out,
                                                     MTOT, DIM, HIDDEN, x1);
}

// round 8
// speedup vs baseline: 4.5081x; 1.5358x over previous
#include <cuda_runtime.h>
#include <cuda_bf16.h>
#include <math.h>
#include <stdint.h>

#define BZ 32
#define HH 56
#define WW 56
#define DIM 256
#define HEADS 8
#define WS 7
#define SHIFT 3
#define NTOK 49
#define NWIN 64
#define HEAD_DIM 32
#define HIDDEN 1024
#define MTOT (BZ*HH*WW)    // 100352 rows

typedef __nv_bfloat16 bf16;

// ---------------- scratch ----------------------------------------------------
__device__ bf16  g_hwin[(size_t)MTOT * DIM];
__device__ bf16  g_qkv [(size_t)MTOT * 3 * DIM];
__device__ bf16  g_attn[(size_t)MTOT * DIM];
__device__ float g_x1  [(size_t)MTOT * DIM];
__device__ bf16  g_h2  [(size_t)MTOT * HIDDEN];
__device__ bf16  g_wqkv[3 * DIM * DIM];
__device__ bf16  g_wproj[DIM * DIM];
__device__ bf16  g_wfc1[HIDDEN * DIM];
__device__ bf16  g_wfc2[DIM * HIDDEN];
__device__ bf16  g_comb[64 * 8 * 64 * 64];   // per (window-in-image, head) bias+mask, padded

__device__ __forceinline__ int remap_row(int m) {
    int b    = m / (NWIN * NTOK);
    int rem  = m - b * (NWIN * NTOK);
    int wimg = rem / NTOK;
    int n    = rem - wimg * NTOK;
    int hh = (wimg >> 3) * WS + n / WS + SHIFT; if (hh >= HH) hh -= HH;
    int ww = (wimg & 7) * WS + n % WS + SHIFT;  if (ww >= WW) ww -= WW;
    return b * (HH * WW) + hh * WW + ww;
}

// ---------------- ptx helpers -------------------------------------------------
__device__ __forceinline__ uint32_t smem_u32(const void* p) {
    return (uint32_t)__cvta_generic_to_shared(p);
}
__device__ __forceinline__ void cp16(uint32_t dst, const void* src) {
    asm volatile("cp.async.cg.shared.global [%0], [%1], 16;\n" :: "r"(dst), "l"(src));
}
__device__ __forceinline__ void cp_commit() { asm volatile("cp.async.commit_group;\n"); }
template<int N> __device__ __forceinline__ void cp_wait() {
    asm volatile("cp.async.wait_group %0;\n" :: "n"(N));
}
__device__ __forceinline__ void ldsm4(uint32_t* r, uint32_t addr) {
    asm volatile("ldmatrix.sync.aligned.m8n8.x4.shared.b16 {%0,%1,%2,%3}, [%4];"
                 : "=r"(r[0]), "=r"(r[1]), "=r"(r[2]), "=r"(r[3]) : "r"(addr));
}
__device__ __forceinline__ void mma_bf16(float* d, const uint32_t* a, const uint32_t* b) {
    asm volatile(
        "mma.sync.aligned.m16n8k16.row.col.f32.bf16.bf16.f32 "
        "{%0,%1,%2,%3}, {%4,%5,%6,%7}, {%8,%9}, {%0,%1,%2,%3};\n"
        : "+f"(d[0]), "+f"(d[1]), "+f"(d[2]), "+f"(d[3])
        : "r"(a[0]), "r"(a[1]), "r"(a[2]), "r"(a[3]), "r"(b[0]), "r"(b[1]));
}
__device__ __forceinline__ uint32_t pack_bf16x2(float a, float b) {
    __nv_bfloat162 h;
    h.x = __float2bfloat16(a); h.y = __float2bfloat16(b);
    return *(uint32_t*)&h;
}

// ---------------- fp32 -> bf16 weight convert (fused, 4 segs) -----------------
__global__ void cvt4_kernel(const float* s0, bf16* d0, int n0,
                            const float* s1, bf16* d1, int n1,
                            const float* s2, bf16* d2, int n2,
                            const float* s3, bf16* d3, int n3) {
    const float* s; bf16* d; int n;
    switch (blockIdx.y) {
        case 0: s = s0; d = d0; n = n0; break;
        case 1: s = s1; d = d1; n = n1; break;
        case 2: s = s2; d = d2; n = n2; break;
        default: s = s3; d = d3; n = n3; break;
    }
    int i = (blockIdx.x * blockDim.x + threadIdx.x) * 4;
    if (i < n) {
        float4 v = *(const float4*)(s + i);
        __nv_bfloat162 p0 = {__float2bfloat16(v.x), __float2bfloat16(v.y)};
        __nv_bfloat162 p1 = {__float2bfloat16(v.z), __float2bfloat16(v.w)};
        *(__nv_bfloat162*)(d + i)     = p0;
        *(__nv_bfloat162*)(d + i + 2) = p1;
    }
}

// ---------------- comb bias precompute ---------------------------------------
// comb[w][h][n][m] = rpb[rel_idx[n,m], h] + mask[w][n,m], -1e30 outside 49x49
__global__ void comb_kernel(const float* __restrict__ rpb,
                            const int* __restrict__ relix,
                            const float* __restrict__ mask,
                            bf16* __restrict__ comb) {
    int w = blockIdx.x, h = blockIdx.y;
    const float* mw = mask + w * (NTOK * NTOK);
    size_t base = ((size_t)(w * 8 + h)) << 12;   // * 4096
    for (int e = threadIdx.x; e < 4096; e += 256) {
        int n = e >> 6, m = e & 63;
        float v = -1e30f;
        if (n < NTOK && m < NTOK)
            v = rpb[relix[n * NTOK + m] * HEADS + h] + mw[n * NTOK + m];
        comb[base + e] = __float2bfloat16(v);
    }
}

// ---------------- LayerNorm (warp per row, bf16 out) -------------------------
template<bool SHIFTMAP>
__global__ void __launch_bounds__(256) ln_kernel(const float* __restrict__ x,
                                                 const float* __restrict__ gw,
                                                 const float* __restrict__ gb,
                                                 bf16* __restrict__ out) {
    int warp = threadIdx.x >> 5, lane = threadIdx.x & 31;
    int m = blockIdx.x * 8 + warp;
    const float* xr;
    if (SHIFTMAP) {
        int r = remap_row(m);
        xr = x + (size_t)r * DIM;
    } else {
        xr = x + (size_t)m * DIM;
    }
    float4 v0 = *(const float4*)(xr + lane * 4);
    float4 v1 = *(const float4*)(xr + 128 + lane * 4);
    float s  = v0.x + v0.y + v0.z + v0.w + v1.x + v1.y + v1.z + v1.w;
    float sq = v0.x*v0.x + v0.y*v0.y + v0.z*v0.z + v0.w*v0.w
             + v1.x*v1.x + v1.y*v1.y + v1.z*v1.z + v1.w*v1.w;
    #pragma unroll
    for (int o = 16; o; o >>= 1) {
        s  += __shfl_xor_sync(0xffffffffu, s,  o);
        sq += __shfl_xor_sync(0xffffffffu, sq, o);
    }
    float mu  = s * (1.0f / DIM);
    float var = sq * (1.0f / DIM) - mu * mu;
    float rs  = rsqrtf(var + 1e-5f);
    float4 w0 = *(const float4*)(gw + lane * 4);
    float4 w1 = *(const float4*)(gw + 128 + lane * 4);
    float4 b0 = *(const float4*)(gb + lane * 4);
    float4 b1 = *(const float4*)(gb + 128 + lane * 4);
    bf16* orow = out + (size_t)m * DIM;
    __nv_bfloat162 p;
    p = {__float2bfloat16((v0.x-mu)*rs*w0.x+b0.x), __float2bfloat16((v0.y-mu)*rs*w0.y+b0.y)};
    *(__nv_bfloat162*)(orow + lane*4)     = p;
    p = {__float2bfloat16((v0.z-mu)*rs*w0.z+b0.z), __float2bfloat16((v0.w-mu)*rs*w0.w+b0.w)};
    *(__nv_bfloat162*)(orow + lane*4 + 2) = p;
    p = {__float2bfloat16((v1.x-mu)*rs*w1.x+b1.x), __float2bfloat16((v1.y-mu)*rs*w1.y+b1.y)};
    *(__nv_bfloat162*)(orow + 128 + lane*4)     = p;
    p = {__float2bfloat16((v1.z-mu)*rs*w1.z+b1.z), __float2bfloat16((v1.w-mu)*rs*w1.w+b1.w)};
    *(__nv_bfloat162*)(orow + 128 + lane*4 + 2) = p;
}

// ---------------- bf16 mma.sync GEMM (NT), CTA 128x256, BK=32, 4-stage -------
#define SROW 80
#define ASTAGE (128 * SROW)
#define BSTAGE (256 * SROW)
#define STAGEB (ASTAGE + BSTAGE)
#define NSTAGE 4
#define SMEM_DYN (NSTAGE * STAGEB)  // 122880

template<int EPI>
__global__ void __launch_bounds__(256, 1) bgemm(const bf16* __restrict__ A,
                                               const bf16* __restrict__ Bm,
                                               const float* __restrict__ bias,
                                               void* __restrict__ Cv,
                                               int M, int N, int K,
                                               const float* __restrict__ res) {
    extern __shared__ __align__(16) char smem[];
    uint32_t sbase = smem_u32(smem);
    int tid = threadIdx.x;
    int bn = blockIdx.x, bm = blockIdx.y;
    int warp = tid >> 5, lane = tid & 31;
    int warpM = (warp & 1) * 64;
    int warpN = (warp >> 1) * 64;
    int r = lane >> 2, c = lane & 3;

    int arw[2], acc_[2], brw[4], bcc[4];
    #pragma unroll
    for (int rpt = 0; rpt < 2; rpt++) {
        int ch = tid + rpt * 256;
        arw[rpt] = ch >> 2; acc_[rpt] = ch & 3;
    }
    #pragma unroll
    for (int rpt = 0; rpt < 4; rpt++) {
        int ch = tid + rpt * 256;
        brw[rpt] = ch >> 2; bcc[rpt] = ch & 3;
    }
    const bf16* Abase = A  + (size_t)(bm * 128) * K;
    const bf16* Bbase = Bm + (size_t)(bn * 256) * K;

    uint32_t aoff = (uint32_t)((lane & 15) * SROW + (lane >> 4) * 16);
    uint32_t boff = (uint32_t)(((lane & 7) + ((lane >> 4) << 3)) * SROW + ((lane & 8) ? 16 : 0));

    float acc[4][8][4];
    #pragma unroll
    for (int mi = 0; mi < 4; mi++)
        #pragma unroll
        for (int ni = 0; ni < 8; ni++)
            #pragma unroll
            for (int t = 0; t < 4; t++) acc[mi][ni][t] = 0.0f;

#define FILL(s, k0) do { \
    uint32_t ab = sbase + (s) * STAGEB; \
    uint32_t bb = ab + ASTAGE; \
    _Pragma("unroll") \
    for (int rpt = 0; rpt < 2; rpt++) \
        cp16(ab + arw[rpt] * SROW + acc_[rpt] * 16, \
             Abase + (size_t)arw[rpt] * K + (k0) + acc_[rpt] * 8); \
    _Pragma("unroll") \
    for (int rpt = 0; rpt < 4; rpt++) \
        cp16(bb + brw[rpt] * SROW + bcc[rpt] * 16, \
             Bbase + (size_t)brw[rpt] * K + (k0) + bcc[rpt] * 8); \
} while (0)

    int nk = K >> 5;
    FILL(0, 0);  cp_commit();
    FILL(1, 32); cp_commit();
    FILL(2, 64); cp_commit();

    for (int i = 0; i < nk; i++) {
        cp_wait<2>();
        __syncthreads();
        int buf = i & 3;
        uint32_t Ab = sbase + buf * STAGEB;
        uint32_t Bb = Ab + ASTAGE;
        #pragma unroll
        for (int kk = 0; kk < 2; kk++) {
            uint32_t af[4][4], bfr[4][4];
            #pragma unroll
            for (int mi = 0; mi < 4; mi++)
                ldsm4(af[mi], Ab + (uint32_t)((warpM + mi * 16) * SROW + kk * 32) + aoff);
            #pragma unroll
            for (int p = 0; p < 4; p++)
                ldsm4(bfr[p], Bb + (uint32_t)((warpN + p * 16) * SROW + kk * 32) + boff);
            #pragma unroll
            for (int mi = 0; mi < 4; mi++)
                #pragma unroll
                for (int ni = 0; ni < 8; ni++)
                    mma_bf16(acc[mi][ni], af[mi], &bfr[ni >> 1][(ni & 1) * 2]);
        }
        if (i + 3 < nk) FILL((i + 3) & 3, (i + 3) * 32);
        cp_commit();
    }

    #pragma unroll
    for (int mi = 0; mi < 4; mi++) {
        #pragma unroll
        for (int half = 0; half < 2; half++) {
            int row = bm * 128 + warpM + mi * 16 + r + half * 8;
            int orow = row;
            if (EPI == 2) orow = remap_row(row);
            const float* rr = (EPI == 2 || EPI == 3) ? res + (size_t)orow * N : nullptr;
            #pragma unroll
            for (int ni = 0; ni < 8; ni++) {
                int col = bn * 256 + warpN + ni * 8 + 2 * c;
                float v0 = acc[mi][ni][half * 2 + 0] + bias[col];
                float v1 = acc[mi][ni][half * 2 + 1] + bias[col + 1];
                if (EPI == 1) {
                    v0 = 0.5f * v0 * (1.0f + erff(v0 * 0.70710678118654752f));
                    v1 = 0.5f * v1 * (1.0f + erff(v1 * 0.70710678118654752f));
                }
                if (EPI == 2 || EPI == 3) {
                    v0 += rr[col];
                    v1 += rr[col + 1];
                }
                if (EPI == 0 || EPI == 1) {
                    bf16* cp = (bf16*)Cv + (size_t)orow * N;
                    __nv_bfloat162 pk = {__float2bfloat16(v0), __float2bfloat16(v1)};
                    *(__nv_bfloat162*)(cp + col) = pk;
                } else {
                    float* cp = (float*)Cv + (size_t)orow * N;
                    *(float2*)(cp + col) = make_float2(v0, v1);
                }
            }
        }
    }
#undef FILL
}

// ---------------- tensor-core windowed attention ------------------------------
// block = (window, head-pair). 8 warps: warp w -> head (w>>2), rows (w&3)*16..+15.
// smem: Q,K [2][64 rows x 80B], VT [2][32 x 144B], comb bias [2][64 x 144B].
__global__ void __launch_bounds__(256) attn_tc(const bf16* __restrict__ qkv,
                                               const bf16* __restrict__ comb,
                                               bf16* __restrict__ out) {
    __shared__ __align__(16) bf16 sQ[2][64 * 40];
    __shared__ __align__(16) bf16 sK[2][64 * 40];
    __shared__ __align__(16) bf16 sVT[2][32 * 72];
    __shared__ __align__(16) bf16 sB[2][64 * 72];

    int tid = threadIdx.x;
    int win = blockIdx.x;
    int hg  = blockIdx.y * 2;
    int w64 = win & 63;

    // ---- zero pads ----
    uint32_t* vz = (uint32_t*)sVT;
    for (int i = tid; i < 2 * 32 * 72 / 2; i += 256) vz[i] = 0;   // whole VT
    for (int i = tid; i < 600; i += 256) {                         // Q,K rows 49..63
        int h = i / 300, rm = i % 300;
        int row = 49 + rm / 20, w = rm % 20;
        ((uint32_t*)sQ)[h * 1280 + row * 20 + w] = 0;
        ((uint32_t*)sK)[h * 1280 + row * 20 + w] = 0;
    }
    __syncthreads();

    // ---- fill Q, K ----
    for (int i = tid; i < 392; i += 256) {
        int h = i / 196, rm = i % 196;
        int tok = rm >> 2, ch = rm & 3;
        const bf16* src = qkv + (size_t)(win * 49 + tok) * 768 + (hg + h) * 32 + ch * 8;
        *(uint4*)((char*)sQ + h * 5120 + tok * 80 + ch * 16) = *(const uint4*)src;
        *(uint4*)((char*)sK + h * 5120 + tok * 80 + ch * 16) = *(const uint4*)(src + 256);
    }
    // ---- fill VT (transposed) ----
    for (int i = tid; i < 1568; i += 256) {
        int h = i / 784, rm = i % 784;
        int tok = rm / 16, dp = (rm % 16) * 2;
        __nv_bfloat162 v = *(const __nv_bfloat162*)(qkv + (size_t)(win * 49 + tok) * 768
                                                    + 512 + (hg + h) * 32 + dp);
        *(bf16*)((char*)sVT + h * 4608 + dp * 144 + tok * 2)       = v.x;
        *(bf16*)((char*)sVT + h * 4608 + (dp + 1) * 144 + tok * 2) = v.y;
    }
    // ---- fill bias ----
    for (int i = tid; i < 1024; i += 256) {
        int h = i >> 9, rm = i & 511;
        int n = rm >> 3, ch = rm & 7;
        const bf16* src = comb + (((size_t)((w64 * 8 + hg + h) * 64 + n)) << 6) + ch * 8;
        *(uint4*)((char*)sB + h * 9216 + n * 144 + ch * 16) = *(const uint4*)src;
    }
    __syncthreads();

    int warp = tid >> 5, lane = tid & 31;
    int head = warp >> 2;
    int rowbase = (warp & 3) * 16;

    uint32_t Qb = smem_u32(sQ) + head * 5120;
    uint32_t Kb = smem_u32(sK) + head * 5120;
    uint32_t Vb = smem_u32(sVT) + head * 4608;
    uint32_t Bb = smem_u32(sB) + head * 9216;

    uint32_t aoff80  = (uint32_t)((lane & 15) * 80 + (lane >> 4) * 16);
    uint32_t aoff144 = (uint32_t)((lane & 15) * 144 + (lane >> 4) * 16);
    uint32_t boff80  = (uint32_t)(((lane & 7) + ((lane >> 4) << 3)) * 80 + ((lane & 8) ? 16 : 0));
    uint32_t boff144 = (uint32_t)(((lane & 7) + ((lane >> 4) << 3)) * 144 + ((lane & 8) ? 16 : 0));

    // ---- S = Q @ K^T ----
    float sacc[8][4];
    #pragma unroll
    for (int ni = 0; ni < 8; ni++)
        #pragma unroll
        for (int t = 0; t < 4; t++) sacc[ni][t] = 0.0f;

    #pragma unroll
    for (int ks = 0; ks < 2; ks++) {
        uint32_t aq[4], bk[4][4];
        ldsm4(aq, Qb + (uint32_t)(rowbase * 80 + ks * 32) + aoff80);
        #pragma unroll
        for (int p = 0; p < 4; p++)
            ldsm4(bk[p], Kb + (uint32_t)(p * 16 * 80 + ks * 32) + boff80);
        #pragma unroll
        for (int ni = 0; ni < 8; ni++)
            mma_bf16(sacc[ni], aq, &bk[ni >> 1][(ni & 1) * 2]);
    }

    // ---- scale + bias ----
    const float scale = 0.17677669529663687f;   // 1/sqrt(32)
    #pragma unroll
    for (int cg = 0; cg < 4; cg++) {
        uint32_t bb[4];
        ldsm4(bb, Bb + (uint32_t)(rowbase * 144 + cg * 32) + aoff144);
        float2 f;
        f = __bfloat1622float2(*(__nv_bfloat162*)&bb[0]);
        sacc[2*cg][0] = sacc[2*cg][0] * scale + f.x;
        sacc[2*cg][1] = sacc[2*cg][1] * scale + f.y;
        f = __bfloat1622float2(*(__nv_bfloat162*)&bb[1]);
        sacc[2*cg][2] = sacc[2*cg][2] * scale + f.x;
        sacc[2*cg][3] = sacc[2*cg][3] * scale + f.y;
        f = __bfloat1622float2(*(__nv_bfloat162*)&bb[2]);
        sacc[2*cg+1][0] = sacc[2*cg+1][0] * scale + f.x;
        sacc[2*cg+1][1] = sacc[2*cg+1][1] * scale + f.y;
        f = __bfloat1622float2(*(__nv_bfloat162*)&bb[3]);
        sacc[2*cg+1][2] = sacc[2*cg+1][2] * scale + f.x;
        sacc[2*cg+1][3] = sacc[2*cg+1][3] * scale + f.y;
    }

    // ---- softmax (two row-halves: regs 0,1 = row r; regs 2,3 = row r+8) ----
    #pragma unroll
    for (int hf = 0; hf < 2; hf++) {
        int i0 = hf * 2;
        float mx = -1e30f;
        #pragma unroll
        for (int ni = 0; ni < 8; ni++)
            mx = fmaxf(mx, fmaxf(sacc[ni][i0], sacc[ni][i0 + 1]));
        mx = fmaxf(mx, __shfl_xor_sync(0xffffffffu, mx, 1));
        mx = fmaxf(mx, __shfl_xor_sync(0xffffffffu, mx, 2));
        float sum = 0.0f;
        #pragma unroll
        for (int ni = 0; ni < 8; ni++) {
            float e0 = expf(sacc[ni][i0] - mx);
            float e1 = expf(sacc[ni][i0 + 1] - mx);
            sacc[ni][i0] = e0; sacc[ni][i0 + 1] = e1;
            sum += e0 + e1;
        }
        sum += __shfl_xor_sync(0xffffffffu, sum, 1);
        sum += __shfl_xor_sync(0xffffffffu, sum, 2);
        float inv = 1.0f / sum;
        #pragma unroll
        for (int ni = 0; ni < 8; ni++) {
            sacc[ni][i0] *= inv; sacc[ni][i0 + 1] *= inv;
        }
    }

    // ---- P fragments (A-layout recycling of C-layout) ----
    uint32_t pa[4][4];
    #pragma unroll
    for (int ks = 0; ks < 4; ks++) {
        pa[ks][0] = pack_bf16x2(sacc[2*ks][0],   sacc[2*ks][1]);
        pa[ks][1] = pack_bf16x2(sacc[2*ks][2],   sacc[2*ks][3]);
        pa[ks][2] = pack_bf16x2(sacc[2*ks+1][0], sacc[2*ks+1][1]);
        pa[ks][3] = pack_bf16x2(sacc[2*ks+1][2], sacc[2*ks+1][3]);
    }

    // ---- O = P @ V ----
    float oacc[4][4];
    #pragma unroll
    for (int ni = 0; ni < 4; ni++)
        #pragma unroll
        for (int t = 0; t < 4; t++) oacc[ni][t] = 0.0f;

    #pragma unroll
    for (int ks = 0; ks < 4; ks++) {
        uint32_t bv[2][4];
        #pragma unroll
        for (int p = 0; p < 2; p++)
            ldsm4(bv[p], Vb + (uint32_t)(p * 16 * 144 + ks * 32) + boff144);
        #pragma unroll
        for (int ni = 0; ni < 4; ni++)
            mma_bf16(oacc[ni], pa[ks], &bv[ni >> 1][(ni & 1) * 2]);
    }

    // ---- store ----
    int gh = hg + head;
    int r0 = rowbase + (lane >> 2);
    #pragma unroll
    for (int ni = 0; ni < 4; ni++) {
        int col = gh * 32 + ni * 8 + (lane & 3) * 2;
        if (r0 < NTOK) {
            __nv_bfloat162 pk = {__float2bfloat16(oacc[ni][0]), __float2bfloat16(oacc[ni][1])};
            *(__nv_bfloat162*)(out + (size_t)(win * 49 + r0) * 256 + col) = pk;
        }
        if (r0 + 8 < NTOK) {
            __nv_bfloat162 pk = {__float2bfloat16(oacc[ni][2]), __float2bfloat16(oacc[ni][3])};
            *(__nv_bfloat162*)(out + (size_t)(win * 49 + r0 + 8) * 256 + col) = pk;
        }
    }
}

// ---------------- launcher ---------------------------------------------------
extern "C" void kernel_launch(void* const* d_in, const int* in_sizes, int n_in,
                              void* d_out, int out_size) {
    const float* x     = (const float*)d_in[0];
    const float* n1w   = (const float*)d_in[1];
    const float* n1b   = (const float*)d_in[2];
    const float* qkvw  = (const float*)d_in[3];
    const float* qkvb  = (const float*)d_in[4];
    const float* rpb   = (const float*)d_in[5];
    const float* projw = (const float*)d_in[6];
    const float* projb = (const float*)d_in[7];
    const float* n2w   = (const float*)d_in[8];
    const float* n2b   = (const float*)d_in[9];
    const float* fc1w  = (const float*)d_in[10];
    const float* fc1b  = (const float*)d_in[11];
    const float* fc2w  = (const float*)d_in[12];
    const float* fc2b  = (const float*)d_in[13];
    const int*   relix = (const int*)d_in[14];
    const float* amask = (const float*)d_in[15];
    float* out = (float*)d_out;

    bf16 *hwin, *qkv, *attn, *h2, *wqkv, *wproj, *wfc1, *wfc2, *comb;
    float *x1;
    cudaGetSymbolAddress((void**)&hwin, g_hwin);
    cudaGetSymbolAddress((void**)&qkv,  g_qkv);
    cudaGetSymbolAddress((void**)&attn, g_attn);
    cudaGetSymbolAddress((void**)&x1,   g_x1);
    cudaGetSymbolAddress((void**)&h2,   g_h2);
    cudaGetSymbolAddress((void**)&wqkv, g_wqkv);
    cudaGetSymbolAddress((void**)&wproj, g_wproj);
    cudaGetSymbolAddress((void**)&wfc1, g_wfc1);
    cudaGetSymbolAddress((void**)&wfc2, g_wfc2);
    cudaGetSymbolAddress((void**)&comb, g_comb);

    cudaFuncSetAttribute(bgemm<0>, cudaFuncAttributeMaxDynamicSharedMemorySize, SMEM_DYN);
    cudaFuncSetAttribute(bgemm<1>, cudaFuncAttributeMaxDynamicSharedMemorySize, SMEM_DYN);
    cudaFuncSetAttribute(bgemm<2>, cudaFuncAttributeMaxDynamicSharedMemorySize, SMEM_DYN);
    cudaFuncSetAttribute(bgemm<3>, cudaFuncAttributeMaxDynamicSharedMemorySize, SMEM_DYN);

    // weight conversion + combined bias precompute
    cvt4_kernel<<<dim3(DIM * HIDDEN / 4 / 256, 4), 256>>>(
        qkvw, wqkv, 3 * DIM * DIM,
        projw, wproj, DIM * DIM,
        fc1w, wfc1, HIDDEN * DIM,
        fc2w, wfc2, DIM * HIDDEN);
    comb_kernel<<<dim3(64, 8), 256>>>(rpb, relix, amask, comb);

    // 1. LN1 + shift + window-partition (bf16 out)
    ln_kernel<true><<<MTOT / 8, 256>>>(x, n1w, n1b, hwin);
    // 2. QKV GEMM -> bf16
    bgemm<0><<<dim3(3, MTOT / 128), 256, SMEM_DYN>>>(hwin, wqkv, qkvb, qkv,
                                                     MTOT, 3 * DIM, DIM, nullptr);
    // 3. tensor-core windowed attention
    attn_tc<<<dim3(BZ * NWIN, 4), 256>>>(qkv, comb, attn);
    // 4. proj GEMM + window-reverse scatter + residual -> f32
    bgemm<2><<<dim3(1, MTOT / 128), 256, SMEM_DYN>>>(attn, wproj, projb, x1,
                                                     MTOT, DIM, DIM, x);
    // 5. LN2 (bf16 out)
    ln_kernel<false><<<MTOT / 8, 256>>>(x1, n2w, n2b, hwin);
    // 6. FC1 + GELU -> bf16
    bgemm<1><<<dim3(4, MTOT / 128), 256, SMEM_DYN>>>(hwin, wfc1, fc1b, h2,
                                                     MTOT, HIDDEN, DIM, nullptr);
    // 7. FC2 + residual -> out (f32)
    bgemm<3><<<dim3(1, MTOT / 128), 256, SMEM_DYN>>>(h2, wfc2, fc2b, out,
                                                     MTOT, DIM, HIDDEN, x1);
}

// round 9
// speedup vs baseline: 4.5314x; 1.0052x over previous
#include <cuda_runtime.h>
#include <cuda_bf16.h>
#include <math.h>
#include <stdint.h>

#define BZ 32
#define HH 56
#define WW 56
#define DIM 256
#define HEADS 8
#define WS 7
#define SHIFT 3
#define NTOK 49
#define NWIN 64
#define HEAD_DIM 32
#define HIDDEN 1024
#define MTOT (BZ*HH*WW)    // 100352 rows

typedef __nv_bfloat16 bf16;

// ---------------- scratch ----------------------------------------------------
__device__ bf16  g_hwin[(size_t)MTOT * DIM];
__device__ bf16  g_qkv [(size_t)MTOT * 3 * DIM];
__device__ bf16  g_attn[(size_t)MTOT * DIM];
__device__ float g_x1  [(size_t)MTOT * DIM];
__device__ bf16  g_h2  [(size_t)MTOT * HIDDEN];
__device__ bf16  g_wqkv[3 * DIM * DIM];
__device__ bf16  g_wproj[DIM * DIM];
__device__ bf16  g_wfc1[HIDDEN * DIM];
__device__ bf16  g_wfc2[DIM * HIDDEN];
__device__ bf16  g_comb[64 * 8 * 64 * 64];

__device__ __forceinline__ int remap_row(int m) {
    int b    = m / (NWIN * NTOK);
    int rem  = m - b * (NWIN * NTOK);
    int wimg = rem / NTOK;
    int n    = rem - wimg * NTOK;
    int hh = (wimg >> 3) * WS + n / WS + SHIFT; if (hh >= HH) hh -= HH;
    int ww = (wimg & 7) * WS + n % WS + SHIFT;  if (ww >= WW) ww -= WW;
    return b * (HH * WW) + hh * WW + ww;
}

// ---------------- ptx helpers -------------------------------------------------
__device__ __forceinline__ uint32_t smem_u32(const void* p) {
    return (uint32_t)__cvta_generic_to_shared(p);
}
__device__ __forceinline__ void cp16(uint32_t dst, const void* src) {
    asm volatile("cp.async.cg.shared.global [%0], [%1], 16;\n" :: "r"(dst), "l"(src));
}
__device__ __forceinline__ void cp_commit() { asm volatile("cp.async.commit_group;\n"); }
template<int N> __device__ __forceinline__ void cp_wait() {
    asm volatile("cp.async.wait_group %0;\n" :: "n"(N));
}
__device__ __forceinline__ void ldsm4(uint32_t* r, uint32_t addr) {
    asm volatile("ldmatrix.sync.aligned.m8n8.x4.shared.b16 {%0,%1,%2,%3}, [%4];"
                 : "=r"(r[0]), "=r"(r[1]), "=r"(r[2]), "=r"(r[3]) : "r"(addr));
}
__device__ __forceinline__ void mma_bf16(float* d, const uint32_t* a, const uint32_t* b) {
    asm volatile(
        "mma.sync.aligned.m16n8k16.row.col.f32.bf16.bf16.f32 "
        "{%0,%1,%2,%3}, {%4,%5,%6,%7}, {%8,%9}, {%0,%1,%2,%3};\n"
        : "+f"(d[0]), "+f"(d[1]), "+f"(d[2]), "+f"(d[3])
        : "r"(a[0]), "r"(a[1]), "r"(a[2]), "r"(a[3]), "r"(b[0]), "r"(b[1]));
}
__device__ __forceinline__ uint32_t pack_bf16x2(float a, float b) {
    __nv_bfloat162 h;
    h.x = __float2bfloat16(a); h.y = __float2bfloat16(b);
    return *(uint32_t*)&h;
}

// ---------------- fp32 -> bf16 weight convert (fused, 4 segs) -----------------
__global__ void cvt4_kernel(const float* s0, bf16* d0, int n0,
                            const float* s1, bf16* d1, int n1,
                            const float* s2, bf16* d2, int n2,
                            const float* s3, bf16* d3, int n3) {
    const float* s; bf16* d; int n;
    switch (blockIdx.y) {
        case 0: s = s0; d = d0; n = n0; break;
        case 1: s = s1; d = d1; n = n1; break;
        case 2: s = s2; d = d2; n = n2; break;
        default: s = s3; d = d3; n = n3; break;
    }
    int i = (blockIdx.x * blockDim.x + threadIdx.x) * 4;
    if (i < n) {
        float4 v = *(const float4*)(s + i);
        __nv_bfloat162 p0 = {__float2bfloat16(v.x), __float2bfloat16(v.y)};
        __nv_bfloat162 p1 = {__float2bfloat16(v.z), __float2bfloat16(v.w)};
        *(__nv_bfloat162*)(d + i)     = p0;
        *(__nv_bfloat162*)(d + i + 2) = p1;
    }
}

// ---------------- comb bias precompute ---------------------------------------
__global__ void comb_kernel(const float* __restrict__ rpb,
                            const int* __restrict__ relix,
                            const float* __restrict__ mask,
                            bf16* __restrict__ comb) {
    int w = blockIdx.x, h = blockIdx.y;
    const float* mw = mask + w * (NTOK * NTOK);
    size_t base = ((size_t)(w * 8 + h)) << 12;
    for (int e = threadIdx.x; e < 4096; e += 256) {
        int n = e >> 6, m = e & 63;
        float v = -1e30f;
        if (n < NTOK && m < NTOK)
            v = rpb[relix[n * NTOK + m] * HEADS + h] + mw[n * NTOK + m];
        comb[base + e] = __float2bfloat16(v);
    }
}

// ---------------- LayerNorm (warp per row, bf16 out) -------------------------
template<bool SHIFTMAP>
__global__ void __launch_bounds__(256) ln_kernel(const float* __restrict__ x,
                                                 const float* __restrict__ gw,
                                                 const float* __restrict__ gb,
                                                 bf16* __restrict__ out) {
    int warp = threadIdx.x >> 5, lane = threadIdx.x & 31;
    int m = blockIdx.x * 8 + warp;
    const float* xr;
    if (SHIFTMAP) {
        int r = remap_row(m);
        xr = x + (size_t)r * DIM;
    } else {
        xr = x + (size_t)m * DIM;
    }
    float4 v0 = *(const float4*)(xr + lane * 4);
    float4 v1 = *(const float4*)(xr + 128 + lane * 4);
    float s  = v0.x + v0.y + v0.z + v0.w + v1.x + v1.y + v1.z + v1.w;
    float sq = v0.x*v0.x + v0.y*v0.y + v0.z*v0.z + v0.w*v0.w
             + v1.x*v1.x + v1.y*v1.y + v1.z*v1.z + v1.w*v1.w;
    #pragma unroll
    for (int o = 16; o; o >>= 1) {
        s  += __shfl_xor_sync(0xffffffffu, s,  o);
        sq += __shfl_xor_sync(0xffffffffu, sq, o);
    }
    float mu  = s * (1.0f / DIM);
    float var = sq * (1.0f / DIM) - mu * mu;
    float rs  = rsqrtf(var + 1e-5f);
    float4 w0 = *(const float4*)(gw + lane * 4);
    float4 w1 = *(const float4*)(gw + 128 + lane * 4);
    float4 b0 = *(const float4*)(gb + lane * 4);
    float4 b1 = *(const float4*)(gb + 128 + lane * 4);
    bf16* orow = out + (size_t)m * DIM;
    __nv_bfloat162 p;
    p = {__float2bfloat16((v0.x-mu)*rs*w0.x+b0.x), __float2bfloat16((v0.y-mu)*rs*w0.y+b0.y)};
    *(__nv_bfloat162*)(orow + lane*4)     = p;
    p = {__float2bfloat16((v0.z-mu)*rs*w0.z+b0.z), __float2bfloat16((v0.w-mu)*rs*w0.w+b0.w)};
    *(__nv_bfloat162*)(orow + lane*4 + 2) = p;
    p = {__float2bfloat16((v1.x-mu)*rs*w1.x+b1.x), __float2bfloat16((v1.y-mu)*rs*w1.y+b1.y)};
    *(__nv_bfloat162*)(orow + 128 + lane*4)     = p;
    p = {__float2bfloat16((v1.z-mu)*rs*w1.z+b1.z), __float2bfloat16((v1.w-mu)*rs*w1.w+b1.w)};
    *(__nv_bfloat162*)(orow + 128 + lane*4 + 2) = p;
}

// ---------------- bf16 mma.sync GEMM (NT), CTA 128x256, BK=64, 3-stage -------
// Fragment double-buffering inside each stage; FILL issued before compute.
#define SROW 144                    // 128B data + 16B pad
#define ASTAGE (128 * SROW)         // 18432
#define BSTAGE (256 * SROW)         // 36864
#define STAGEB (ASTAGE + BSTAGE)    // 55296
#define NSTAGE 3
#define SMEM_DYN (NSTAGE * STAGEB)  // 165888

template<int EPI>
__global__ void __launch_bounds__(256, 1) bgemm(const bf16* __restrict__ A,
                                               const bf16* __restrict__ Bm,
                                               const float* __restrict__ bias,
                                               void* __restrict__ Cv,
                                               int M, int N, int K,
                                               const float* __restrict__ res) {
    extern __shared__ __align__(16) char smem[];
    uint32_t sbase = smem_u32(smem);
    int tid = threadIdx.x;
    int bn = blockIdx.x, bm = blockIdx.y;
    int warp = tid >> 5, lane = tid & 31;
    int warpM = (warp & 1) * 64;
    int warpN = (warp >> 1) * 64;
    int r = lane >> 2, c = lane & 3;

    // fill coords: BK=64 -> A: 1024 16B-chunks (4/thr), B: 2048 (8/thr)
    int arw[4], acc_[4], brw[8], bcc[8];
    #pragma unroll
    for (int rpt = 0; rpt < 4; rpt++) {
        int ch = tid + rpt * 256;
        arw[rpt] = ch >> 3; acc_[rpt] = ch & 7;
    }
    #pragma unroll
    for (int rpt = 0; rpt < 8; rpt++) {
        int ch = tid + rpt * 256;
        brw[rpt] = ch >> 3; bcc[rpt] = ch & 7;
    }
    const bf16* Abase = A  + (size_t)(bm * 128) * K;
    const bf16* Bbase = Bm + (size_t)(bn * 256) * K;

    uint32_t aoff = (uint32_t)((lane & 15) * SROW + (lane >> 4) * 16);
    uint32_t boff = (uint32_t)(((lane & 7) + ((lane >> 4) << 3)) * SROW + ((lane & 8) ? 16 : 0));

    float acc[4][8][4];
    #pragma unroll
    for (int mi = 0; mi < 4; mi++)
        #pragma unroll
        for (int ni = 0; ni < 8; ni++)
            #pragma unroll
            for (int t = 0; t < 4; t++) acc[mi][ni][t] = 0.0f;

#define FILL(s, k0) do { \
    uint32_t ab = sbase + (s) * STAGEB; \
    uint32_t bb = ab + ASTAGE; \
    _Pragma("unroll") \
    for (int rpt = 0; rpt < 4; rpt++) \
        cp16(ab + arw[rpt] * SROW + acc_[rpt] * 16, \
             Abase + (size_t)arw[rpt] * K + (k0) + acc_[rpt] * 8); \
    _Pragma("unroll") \
    for (int rpt = 0; rpt < 8; rpt++) \
        cp16(bb + brw[rpt] * SROW + bcc[rpt] * 16, \
             Bbase + (size_t)brw[rpt] * K + (k0) + bcc[rpt] * 8); \
} while (0)

    int nk = K >> 6;                  // stages of 64
    FILL(0, 0);  cp_commit();
    FILL(1, 64); cp_commit();

    int stage = 0, fstage = 2;
    for (int i = 0; i < nk; i++) {
        cp_wait<1>();
        __syncthreads();
        // issue next-next stage loads first (overlaps with compute below)
        if (i + 2 < nk) {
            FILL(fstage, (i + 2) * 64);
        }
        cp_commit();

        uint32_t Ab = sbase + stage * STAGEB;
        uint32_t Bb = Ab + ASTAGE;

        uint32_t af[2][4][4], bfr[2][4][4];
        // prefetch kk=0 fragments
        #pragma unroll
        for (int mi = 0; mi < 4; mi++)
            ldsm4(af[0][mi], Ab + (uint32_t)((warpM + mi * 16) * SROW) + aoff);
        #pragma unroll
        for (int p = 0; p < 4; p++)
            ldsm4(bfr[0][p], Bb + (uint32_t)((warpN + p * 16) * SROW) + boff);

        #pragma unroll
        for (int kk = 0; kk < 4; kk++) {
            int cur = kk & 1, nxt = cur ^ 1;
            if (kk < 3) {
                #pragma unroll
                for (int mi = 0; mi < 4; mi++)
                    ldsm4(af[nxt][mi],
                          Ab + (uint32_t)((warpM + mi * 16) * SROW + (kk + 1) * 32) + aoff);
                #pragma unroll
                for (int p = 0; p < 4; p++)
                    ldsm4(bfr[nxt][p],
                          Bb + (uint32_t)((warpN + p * 16) * SROW + (kk + 1) * 32) + boff);
            }
            #pragma unroll
            for (int mi = 0; mi < 4; mi++)
                #pragma unroll
                for (int ni = 0; ni < 8; ni++)
                    mma_bf16(acc[mi][ni], af[cur][mi], &bfr[cur][ni >> 1][(ni & 1) * 2]);
        }

        stage = (stage + 1 == NSTAGE) ? 0 : stage + 1;
        fstage = (fstage + 1 == NSTAGE) ? 0 : fstage + 1;
    }

    // epilogue
    #pragma unroll
    for (int mi = 0; mi < 4; mi++) {
        #pragma unroll
        for (int half = 0; half < 2; half++) {
            int row = bm * 128 + warpM + mi * 16 + r + half * 8;
            int orow = row;
            if (EPI == 2) orow = remap_row(row);
            const float* rr = (EPI == 2 || EPI == 3) ? res + (size_t)orow * N : nullptr;
            #pragma unroll
            for (int ni = 0; ni < 8; ni++) {
                int col = bn * 256 + warpN + ni * 8 + 2 * c;
                float v0 = acc[mi][ni][half * 2 + 0] + bias[col];
                float v1 = acc[mi][ni][half * 2 + 1] + bias[col + 1];
                if (EPI == 1) {
                    v0 = 0.5f * v0 * (1.0f + erff(v0 * 0.70710678118654752f));
                    v1 = 0.5f * v1 * (1.0f + erff(v1 * 0.70710678118654752f));
                }
                if (EPI == 2 || EPI == 3) {
                    v0 += rr[col];
                    v1 += rr[col + 1];
                }
                if (EPI == 0 || EPI == 1) {
                    bf16* cp = (bf16*)Cv + (size_t)orow * N;
                    __nv_bfloat162 pk = {__float2bfloat16(v0), __float2bfloat16(v1)};
                    *(__nv_bfloat162*)(cp + col) = pk;
                } else {
                    float* cp = (float*)Cv + (size_t)orow * N;
                    *(float2*)(cp + col) = make_float2(v0, v1);
                }
            }
        }
    }
#undef FILL
}

// ---------------- tensor-core windowed attention ------------------------------
__global__ void __launch_bounds__(256) attn_tc(const bf16* __restrict__ qkv,
                                               const bf16* __restrict__ comb,
                                               bf16* __restrict__ out) {
    __shared__ __align__(16) bf16 sQ[2][64 * 40];
    __shared__ __align__(16) bf16 sK[2][64 * 40];
    __shared__ __align__(16) bf16 sVT[2][32 * 72];
    __shared__ __align__(16) bf16 sB[2][64 * 72];

    int tid = threadIdx.x;
    int win = blockIdx.x;
    int hg  = blockIdx.y * 2;
    int w64 = win & 63;

    uint32_t* vz = (uint32_t*)sVT;
    for (int i = tid; i < 2 * 32 * 72 / 2; i += 256) vz[i] = 0;
    for (int i = tid; i < 600; i += 256) {
        int h = i / 300, rm = i % 300;
        int row = 49 + rm / 20, w = rm % 20;
        ((uint32_t*)sQ)[h * 1280 + row * 20 + w] = 0;
        ((uint32_t*)sK)[h * 1280 + row * 20 + w] = 0;
    }
    __syncthreads();

    for (int i = tid; i < 392; i += 256) {
        int h = i / 196, rm = i % 196;
        int tok = rm >> 2, ch = rm & 3;
        const bf16* src = qkv + (size_t)(win * 49 + tok) * 768 + (hg + h) * 32 + ch * 8;
        *(uint4*)((char*)sQ + h * 5120 + tok * 80 + ch * 16) = *(const uint4*)src;
        *(uint4*)((char*)sK + h * 5120 + tok * 80 + ch * 16) = *(const uint4*)(src + 256);
    }
    for (int i = tid; i < 1568; i += 256) {
        int h = i / 784, rm = i % 784;
        int tok = rm / 16, dp = (rm % 16) * 2;
        __nv_bfloat162 v = *(const __nv_bfloat162*)(qkv + (size_t)(win * 49 + tok) * 768
                                                    + 512 + (hg + h) * 32 + dp);
        *(bf16*)((char*)sVT + h * 4608 + dp * 144 + tok * 2)       = v.x;
        *(bf16*)((char*)sVT + h * 4608 + (dp + 1) * 144 + tok * 2) = v.y;
    }
    for (int i = tid; i < 1024; i += 256) {
        int h = i >> 9, rm = i & 511;
        int n = rm >> 3, ch = rm & 7;
        const bf16* src = comb + (((size_t)((w64 * 8 + hg + h) * 64 + n)) << 6) + ch * 8;
        *(uint4*)((char*)sB + h * 9216 + n * 144 + ch * 16) = *(const uint4*)src;
    }
    __syncthreads();

    int warp = tid >> 5, lane = tid & 31;
    int head = warp >> 2;
    int rowbase = (warp & 3) * 16;

    uint32_t Qb = smem_u32(sQ) + head * 5120;
    uint32_t Kb = smem_u32(sK) + head * 5120;
    uint32_t Vb = smem_u32(sVT) + head * 4608;
    uint32_t Bb = smem_u32(sB) + head * 9216;

    uint32_t aoff80  = (uint32_t)((lane & 15) * 80 + (lane >> 4) * 16);
    uint32_t aoff144 = (uint32_t)((lane & 15) * 144 + (lane >> 4) * 16);
    uint32_t boff80  = (uint32_t)(((lane & 7) + ((lane >> 4) << 3)) * 80 + ((lane & 8) ? 16 : 0));
    uint32_t boff144 = (uint32_t)(((lane & 7) + ((lane >> 4) << 3)) * 144 + ((lane & 8) ? 16 : 0));

    float sacc[8][4];
    #pragma unroll
    for (int ni = 0; ni < 8; ni++)
        #pragma unroll
        for (int t = 0; t < 4; t++) sacc[ni][t] = 0.0f;

    #pragma unroll
    for (int ks = 0; ks < 2; ks++) {
        uint32_t aq[4], bk[4][4];
        ldsm4(aq, Qb + (uint32_t)(rowbase * 80 + ks * 32) + aoff80);
        #pragma unroll
        for (int p = 0; p < 4; p++)
            ldsm4(bk[p], Kb + (uint32_t)(p * 16 * 80 + ks * 32) + boff80);
        #pragma unroll
        for (int ni = 0; ni < 8; ni++)
            mma_bf16(sacc[ni], aq, &bk[ni >> 1][(ni & 1) * 2]);
    }

    const float scale = 0.17677669529663687f;
    #pragma unroll
    for (int cg = 0; cg < 4; cg++) {
        uint32_t bb[4];
        ldsm4(bb, Bb + (uint32_t)(rowbase * 144 + cg * 32) + aoff144);
        float2 f;
        f = __bfloat1622float2(*(__nv_bfloat162*)&bb[0]);
        sacc[2*cg][0] = sacc[2*cg][0] * scale + f.x;
        sacc[2*cg][1] = sacc[2*cg][1] * scale + f.y;
        f = __bfloat1622float2(*(__nv_bfloat162*)&bb[1]);
        sacc[2*cg][2] = sacc[2*cg][2] * scale + f.x;
        sacc[2*cg][3] = sacc[2*cg][3] * scale + f.y;
        f = __bfloat1622float2(*(__nv_bfloat162*)&bb[2]);
        sacc[2*cg+1][0] = sacc[2*cg+1][0] * scale + f.x;
        sacc[2*cg+1][1] = sacc[2*cg+1][1] * scale + f.y;
        f = __bfloat1622float2(*(__nv_bfloat162*)&bb[3]);
        sacc[2*cg+1][2] = sacc[2*cg+1][2] * scale + f.x;
        sacc[2*cg+1][3] = sacc[2*cg+1][3] * scale + f.y;
    }

    #pragma unroll
    for (int hf = 0; hf < 2; hf++) {
        int i0 = hf * 2;
        float mx = -1e30f;
        #pragma unroll
        for (int ni = 0; ni < 8; ni++)
            mx = fmaxf(mx, fmaxf(sacc[ni][i0], sacc[ni][i0 + 1]));
        mx = fmaxf(mx, __shfl_xor_sync(0xffffffffu, mx, 1));
        mx = fmaxf(mx, __shfl_xor_sync(0xffffffffu, mx, 2));
        float sum = 0.0f;
        #pragma unroll
        for (int ni = 0; ni < 8; ni++) {
            float e0 = expf(sacc[ni][i0] - mx);
            float e1 = expf(sacc[ni][i0 + 1] - mx);
            sacc[ni][i0] = e0; sacc[ni][i0 + 1] = e1;
            sum += e0 + e1;
        }
        sum += __shfl_xor_sync(0xffffffffu, sum, 1);
        sum += __shfl_xor_sync(0xffffffffu, sum, 2);
        float inv = 1.0f / sum;
        #pragma unroll
        for (int ni = 0; ni < 8; ni++) {
            sacc[ni][i0] *= inv; sacc[ni][i0 + 1] *= inv;
        }
    }

    uint32_t pa[4][4];
    #pragma unroll
    for (int ks = 0; ks < 4; ks++) {
        pa[ks][0] = pack_bf16x2(sacc[2*ks][0],   sacc[2*ks][1]);
        pa[ks][1] = pack_bf16x2(sacc[2*ks][2],   sacc[2*ks][3]);
        pa[ks][2] = pack_bf16x2(sacc[2*ks+1][0], sacc[2*ks+1][1]);
        pa[ks][3] = pack_bf16x2(sacc[2*ks+1][2], sacc[2*ks+1][3]);
    }

    float oacc[4][4];
    #pragma unroll
    for (int ni = 0; ni < 4; ni++)
        #pragma unroll
        for (int t = 0; t < 4; t++) oacc[ni][t] = 0.0f;

    #pragma unroll
    for (int ks = 0; ks < 4; ks++) {
        uint32_t bv[2][4];
        #pragma unroll
        for (int p = 0; p < 2; p++)
            ldsm4(bv[p], Vb + (uint32_t)(p * 16 * 144 + ks * 32) + boff144);
        #pragma unroll
        for (int ni = 0; ni < 4; ni++)
            mma_bf16(oacc[ni], pa[ks], &bv[ni >> 1][(ni & 1) * 2]);
    }

    int gh = hg + head;
    int r0 = rowbase + (lane >> 2);
    #pragma unroll
    for (int ni = 0; ni < 4; ni++) {
        int col = gh * 32 + ni * 8 + (lane & 3) * 2;
        if (r0 < NTOK) {
            __nv_bfloat162 pk = {__float2bfloat16(oacc[ni][0]), __float2bfloat16(oacc[ni][1])};
            *(__nv_bfloat162*)(out + (size_t)(win * 49 + r0) * 256 + col) = pk;
        }
        if (r0 + 8 < NTOK) {
            __nv_bfloat162 pk = {__float2bfloat16(oacc[ni][2]), __float2bfloat16(oacc[ni][3])};
            *(__nv_bfloat162*)(out + (size_t)(win * 49 + r0 + 8) * 256 + col) = pk;
        }
    }
}

// ---------------- launcher ---------------------------------------------------
extern "C" void kernel_launch(void* const* d_in, const int* in_sizes, int n_in,
                              void* d_out, int out_size) {
    const float* x     = (const float*)d_in[0];
    const float* n1w   = (const float*)d_in[1];
    const float* n1b   = (const float*)d_in[2];
    const float* qkvw  = (const float*)d_in[3];
    const float* qkvb  = (const float*)d_in[4];
    const float* rpb   = (const float*)d_in[5];
    const float* projw = (const float*)d_in[6];
    const float* projb = (const float*)d_in[7];
    const float* n2w   = (const float*)d_in[8];
    const float* n2b   = (const float*)d_in[9];
    const float* fc1w  = (const float*)d_in[10];
    const float* fc1b  = (const float*)d_in[11];
    const float* fc2w  = (const float*)d_in[12];
    const float* fc2b  = (const float*)d_in[13];
    const int*   relix = (const int*)d_in[14];
    const float* amask = (const float*)d_in[15];
    float* out = (float*)d_out;

    bf16 *hwin, *qkv, *attn, *h2, *wqkv, *wproj, *wfc1, *wfc2, *comb;
    float *x1;
    cudaGetSymbolAddress((void**)&hwin, g_hwin);
    cudaGetSymbolAddress((void**)&qkv,  g_qkv);
    cudaGetSymbolAddress((void**)&attn, g_attn);
    cudaGetSymbolAddress((void**)&x1,   g_x1);
    cudaGetSymbolAddress((void**)&h2,   g_h2);
    cudaGetSymbolAddress((void**)&wqkv, g_wqkv);
    cudaGetSymbolAddress((void**)&wproj, g_wproj);
    cudaGetSymbolAddress((void**)&wfc1, g_wfc1);
    cudaGetSymbolAddress((void**)&wfc2, g_wfc2);
    cudaGetSymbolAddress((void**)&comb, g_comb);

    cudaFuncSetAttribute(bgemm<0>, cudaFuncAttributeMaxDynamicSharedMemorySize, SMEM_DYN);
    cudaFuncSetAttribute(bgemm<1>, cudaFuncAttributeMaxDynamicSharedMemorySize, SMEM_DYN);
    cudaFuncSetAttribute(bgemm<2>, cudaFuncAttributeMaxDynamicSharedMemorySize, SMEM_DYN);
    cudaFuncSetAttribute(bgemm<3>, cudaFuncAttributeMaxDynamicSharedMemorySize, SMEM_DYN);

    cvt4_kernel<<<dim3(DIM * HIDDEN / 4 / 256, 4), 256>>>(
        qkvw, wqkv, 3 * DIM * DIM,
        projw, wproj, DIM * DIM,
        fc1w, wfc1, HIDDEN * DIM,
        fc2w, wfc2, DIM * HIDDEN);
    comb_kernel<<<dim3(64, 8), 256>>>(rpb, relix, amask, comb);

    // 1. LN1 + shift + window-partition (bf16 out)
    ln_kernel<true><<<MTOT / 8, 256>>>(x, n1w, n1b, hwin);
    // 2. QKV GEMM -> bf16
    bgemm<0><<<dim3(3, MTOT / 128), 256, SMEM_DYN>>>(hwin, wqkv, qkvb, qkv,
                                                     MTOT, 3 * DIM, DIM, nullptr);
    // 3. tensor-core windowed attention
    attn_tc<<<dim3(BZ * NWIN, 4), 256>>>(qkv, comb, attn);
    // 4. proj GEMM + window-reverse scatter + residual -> f32
    bgemm<2><<<dim3(1, MTOT / 128), 256, SMEM_DYN>>>(attn, wproj, projb, x1,
                                                     MTOT, DIM, DIM, x);
    // 5. LN2 (bf16 out)
    ln_kernel<false><<<MTOT / 8, 256>>>(x1, n2w, n2b, hwin);
    // 6. FC1 + GELU -> bf16
    bgemm<1><<<dim3(4, MTOT / 128), 256, SMEM_DYN>>>(hwin, wfc1, fc1b, h2,
                                                     MTOT, HIDDEN, DIM, nullptr);
    // 7. FC2 + residual -> out (f32)
    bgemm<3><<<dim3(1, MTOT / 128), 256, SMEM_DYN>>>(h2, wfc2, fc2b, out,
                                                     MTOT, DIM, HIDDEN, x1);
}